// round 1
// baseline (speedup 1.0000x reference)
#include <cuda_runtime.h>
#include <cuda_bf16.h>
#include <mma.h>

using namespace nvcuda;
using bf16 = __nv_bfloat16;

#define BB  2
#define NN  2048
#define DD  1024
#define HH  8
#define DKK 128
#define DVV 1024

// ---------------- static scratch (no allocations allowed) ----------------
__device__ bf16 g_xb[BB * NN * DD];          // x in bf16         (8 MB)
__device__ bf16 g_wq[HH * DKK * DD];         // Wq bf16           (2 MB)
__device__ bf16 g_wk[HH * DKK * DD];         // Wk bf16           (2 MB)
__device__ bf16 g_wv[HH * DVV * DD];         // Wv bf16           (16 MB)
__device__ bf16 g_Q [BB * HH * NN * DKK];    // [B,H,N,DK]        (8 MB)
__device__ bf16 g_K [BB * HH * NN * DKK];    // [B,H,N,DK]        (8 MB)
__device__ bf16 g_V [BB * HH * NN * DVV];    // [B,H,N,DV]        (64 MB)

// ---------------- fp32 -> bf16 conversion (vectorized) ----------------
__global__ void cvt4_kernel(const float4* __restrict__ in,
                            __nv_bfloat162* __restrict__ out, int n4) {
    int i = blockIdx.x * blockDim.x + threadIdx.x;
    int stride = gridDim.x * blockDim.x;
    for (; i < n4; i += stride) {
        float4 v = in[i];
        out[2 * i]     = __floats2bfloat162_rn(v.x, v.y);
        out[2 * i + 1] = __floats2bfloat162_rn(v.z, v.w);
    }
}

// ---------------- out = x (residual init, vectorized copy) ----------------
__global__ void copy4_kernel(const float4* __restrict__ in,
                             float4* __restrict__ out, int n4) {
    int i = blockIdx.x * blockDim.x + threadIdx.x;
    int stride = gridDim.x * blockDim.x;
    for (; i < n4; i += stride) out[i] = in[i];
}

// ---------------- projection GEMM ----------------
// C[M=4096, F] = Xb[4096,1024] @ Wb[F,1024]^T, written to out[b,h,n,e] bf16.
// CTA tile 128x128, 8 warps (2x4), warp tile 64x32 (4x2 wmma 16x16 frags).
__global__ __launch_bounds__(256)
void proj_kernel(const bf16* __restrict__ A, const bf16* __restrict__ W,
                 bf16* __restrict__ out, int Dh) {
    __shared__ float patch[8][16][20];   // store_matrix ld=20 floats (80B, 16B-mult)
    int wid  = threadIdx.x >> 5;
    int lane = threadIdx.x & 31;
    int warp_m = wid >> 2;          // 0..1
    int warp_f = wid & 3;           // 0..3
    int row0 = blockIdx.y * 128 + warp_m * 64;
    int col0 = blockIdx.x * 128 + warp_f * 32;

    wmma::fragment<wmma::accumulator, 16, 16, 16, float> acc[4][2];
    #pragma unroll
    for (int i = 0; i < 4; i++)
        #pragma unroll
        for (int j = 0; j < 2; j++) wmma::fill_fragment(acc[i][j], 0.0f);

    for (int k = 0; k < DD; k += 16) {
        wmma::fragment<wmma::matrix_a, 16, 16, 16, bf16, wmma::row_major> a[4];
        wmma::fragment<wmma::matrix_b, 16, 16, 16, bf16, wmma::col_major> b[2];
        #pragma unroll
        for (int i = 0; i < 4; i++)
            wmma::load_matrix_sync(a[i], A + (size_t)(row0 + i * 16) * DD + k, DD);
        #pragma unroll
        for (int j = 0; j < 2; j++)
            wmma::load_matrix_sync(b[j], W + (size_t)(col0 + j * 16) * DD + k, DD);
        #pragma unroll
        for (int i = 0; i < 4; i++)
            #pragma unroll
            for (int j = 0; j < 2; j++)
                wmma::mma_sync(acc[i][j], a[i], b[j], acc[i][j]);
    }

    // epilogue: remap (row=b*N+n, col=h*Dh+e) -> [b,h,n,e] bf16
    #pragma unroll
    for (int i = 0; i < 4; i++) {
        #pragma unroll
        for (int j = 0; j < 2; j++) {
            wmma::store_matrix_sync(&patch[wid][0][0], acc[i][j], 20, wmma::mem_row_major);
            __syncwarp();
            for (int t = lane; t < 256; t += 32) {
                int r = t >> 4, c = t & 15;
                int grow = row0 + i * 16 + r;
                int gcol = col0 + j * 16 + c;
                int b_ = grow >> 11;        // / 2048
                int n_ = grow & 2047;
                int h_ = gcol / Dh;
                int e_ = gcol - h_ * Dh;
                out[(((size_t)b_ * HH + h_) * NN + n_) * Dh + e_] =
                    __float2bfloat16(patch[wid][r][c]);
            }
            __syncwarp();
        }
    }
}

// ---------------- fused causal relu-attention ----------------
// Grid: (col_chunk=8, row_tile=32, b*h=16), block 128 (4 warps).
// Per CTA: out[row0:row0+64, col0:col0+128] for one (b,h), looped over causal
// m-tiles of 64. S in fp32 smem -> mask/relu/(1/N) -> bf16 smem -> PV mma.
__global__ __launch_bounds__(128)
void attn_kernel(const bf16* __restrict__ Qg, const bf16* __restrict__ Kg,
                 const bf16* __restrict__ Vg, float* __restrict__ out) {
    __shared__ float sS[64][68];     // ld=68 floats (272B, 16B-mult)
    __shared__ bf16  sSb[64][72];    // ld=72 bf16  (144B, 16B-mult)
    __shared__ float patch[4][16][20];

    int wid  = threadIdx.x >> 5;
    int lane = threadIdx.x & 31;
    int bh = blockIdx.z;
    int b_ = bh >> 3;                // / HH
    int row0 = blockIdx.y * 64;
    int col0 = blockIdx.x * 128;

    const bf16* Qp = Qg + (size_t)bh * NN * DKK;
    const bf16* Kp = Kg + (size_t)bh * NN * DKK;
    const bf16* Vp = Vg + (size_t)bh * NN * DVV;

    // preload this warp's Q rows (16 x 128) as 8 k-frags, kept in registers
    wmma::fragment<wmma::matrix_a, 16, 16, 16, bf16, wmma::row_major> qf[8];
    #pragma unroll
    for (int k = 0; k < 8; k++)
        wmma::load_matrix_sync(qf[k], Qp + (size_t)(row0 + wid * 16) * DKK + k * 16, DKK);

    wmma::fragment<wmma::accumulator, 16, 16, 16, float> oacc[8];
    #pragma unroll
    for (int j = 0; j < 8; j++) wmma::fill_fragment(oacc[j], 0.0f);

    const float inv_n = 1.0f / (float)NN;
    int ntiles = blockIdx.y + 1;     // causal: only m-tiles <= row tile

    for (int mt = 0; mt < ntiles; mt++) {
        int m0 = mt * 64;

        // ---- S = Q @ K^T : warp computes rows [wid*16, +16), cols [0,64) ----
        wmma::fragment<wmma::accumulator, 16, 16, 16, float> sacc[4];
        #pragma unroll
        for (int j = 0; j < 4; j++) wmma::fill_fragment(sacc[j], 0.0f);
        #pragma unroll
        for (int j = 0; j < 4; j++) {
            #pragma unroll
            for (int k = 0; k < 8; k++) {
                wmma::fragment<wmma::matrix_b, 16, 16, 16, bf16, wmma::col_major> kf;
                wmma::load_matrix_sync(kf, Kp + (size_t)(m0 + j * 16) * DKK + k * 16, DKK);
                wmma::mma_sync(sacc[j], qf[k], kf, sacc[j]);
            }
        }
        #pragma unroll
        for (int j = 0; j < 4; j++)
            wmma::store_matrix_sync(&sS[wid * 16][j * 16], sacc[j], 68, wmma::mem_row_major);
        __syncthreads();

        // ---- mask + relu + /N -> bf16 ----
        bool diag = (mt == blockIdx.y);
        for (int t = threadIdx.x; t < 64 * 64; t += 128) {
            int r = t >> 6, c = t & 63;
            float v = fmaxf(sS[r][c], 0.0f) * inv_n;
            if (diag && (m0 + c) > (row0 + r)) v = 0.0f;
            sSb[r][c] = __float2bfloat16(v);
        }
        __syncthreads();

        // ---- out += Sb @ V : warp computes rows [wid*16,+16) x 128 cols ----
        wmma::fragment<wmma::matrix_a, 16, 16, 16, bf16, wmma::row_major> af[4];
        #pragma unroll
        for (int k2 = 0; k2 < 4; k2++)
            wmma::load_matrix_sync(af[k2], &sSb[wid * 16][k2 * 16], 72);
        #pragma unroll
        for (int j = 0; j < 8; j++) {
            #pragma unroll
            for (int k2 = 0; k2 < 4; k2++) {
                wmma::fragment<wmma::matrix_b, 16, 16, 16, bf16, wmma::row_major> vf;
                wmma::load_matrix_sync(vf, Vp + (size_t)(m0 + k2 * 16) * DVV + col0 + j * 16, DVV);
                wmma::mma_sync(oacc[j], af[k2], vf, oacc[j]);
            }
        }
        // no extra sync needed: next iteration's sS store is followed by a
        // __syncthreads() before sSb is overwritten, which also fences phase-2 readers.
    }

    // ---- epilogue: atomicAdd into residual-initialized out ----
    float* op = out + ((size_t)b_ * NN + row0 + wid * 16) * DVV + col0;
    #pragma unroll
    for (int j = 0; j < 8; j++) {
        wmma::store_matrix_sync(&patch[wid][0][0], oacc[j], 20, wmma::mem_row_major);
        __syncwarp();
        for (int t = lane; t < 256; t += 32) {
            int r = t >> 4, c = t & 15;
            atomicAdd(op + (size_t)r * DVV + j * 16 + c, patch[wid][r][c]);
        }
        __syncwarp();
    }
}

// ---------------- launch ----------------
extern "C" void kernel_launch(void* const* d_in, const int* in_sizes, int n_in,
                              void* d_out, int out_size) {
    const float* x  = (const float*)d_in[0];
    const float* Wq = (const float*)d_in[1];
    const float* Wk = (const float*)d_in[2];
    const float* Wv = (const float*)d_in[3];
    float* out = (float*)d_out;

    void* p;
    cudaGetSymbolAddress(&p, g_xb); bf16* xb = (bf16*)p;
    cudaGetSymbolAddress(&p, g_wq); bf16* wq = (bf16*)p;
    cudaGetSymbolAddress(&p, g_wk); bf16* wk = (bf16*)p;
    cudaGetSymbolAddress(&p, g_wv); bf16* wv = (bf16*)p;
    cudaGetSymbolAddress(&p, g_Q);  bf16* Q  = (bf16*)p;
    cudaGetSymbolAddress(&p, g_K);  bf16* K  = (bf16*)p;
    cudaGetSymbolAddress(&p, g_V);  bf16* V  = (bf16*)p;

    const int nx  = BB * NN * DD;        // 4194304
    const int nwq = HH * DKK * DD;       // 1048576
    const int nwv = HH * DVV * DD;       // 8388608

    // fp32 -> bf16 conversions
    cvt4_kernel<<<2048, 256>>>((const float4*)x,  (__nv_bfloat162*)xb, nx  / 4);
    cvt4_kernel<<<1024, 256>>>((const float4*)Wq, (__nv_bfloat162*)wq, nwq / 4);
    cvt4_kernel<<<1024, 256>>>((const float4*)Wk, (__nv_bfloat162*)wk, nwq / 4);
    cvt4_kernel<<<2048, 256>>>((const float4*)Wv, (__nv_bfloat162*)wv, nwv / 4);

    // QKV projections
    proj_kernel<<<dim3(HH * DKK / 128, BB * NN / 128), 256>>>(xb, wq, Q, DKK);
    proj_kernel<<<dim3(HH * DKK / 128, BB * NN / 128), 256>>>(xb, wk, K, DKK);
    proj_kernel<<<dim3(HH * DVV / 128, BB * NN / 128), 256>>>(xb, wv, V, DVV);

    // residual init: out = x
    copy4_kernel<<<2048, 256>>>((const float4*)x, (float4*)out, nx / 4);

    // fused causal relu-attention, heads reduced via atomics
    attn_kernel<<<dim3(DVV / 128, NN / 64, BB * HH), 128>>>(Q, K, V, out);
}

// round 3
// speedup vs baseline: 1.7357x; 1.7357x over previous
#include <cuda_runtime.h>
#include <cuda_bf16.h>
#include <mma.h>
#include <cstdint>

using namespace nvcuda;
using bf16 = __nv_bfloat16;

#define BB  2
#define NN  2048
#define DD  1024
#define HH  8
#define DKK 128
#define DVV 1024

// ---------------- static scratch (no allocations allowed) ----------------
__device__ bf16 g_xb[BB * NN * DD];          // x bf16
__device__ bf16 g_wq[HH * DKK * DD];
__device__ bf16 g_wk[HH * DKK * DD];
__device__ bf16 g_wv[HH * DVV * DD];
__device__ bf16 g_Q [BB * HH * NN * DKK];    // [B,H,N,DK]
__device__ bf16 g_K [BB * HH * NN * DKK];
__device__ bf16 g_V [BB * HH * NN * DVV];    // [B,H,N,DV]

// ---------------- cp.async helpers ----------------
__device__ __forceinline__ void cpa16(void* dst_smem, const void* src_gmem) {
    unsigned d = (unsigned)__cvta_generic_to_shared(dst_smem);
    asm volatile("cp.async.cg.shared.global [%0], [%1], 16;\n" :: "r"(d), "l"(src_gmem));
}
__device__ __forceinline__ void cpa_commit() {
    asm volatile("cp.async.commit_group;\n" ::: "memory");
}
__device__ __forceinline__ void cpa_wait0() {
    asm volatile("cp.async.wait_group 0;\n" ::: "memory");
}
__device__ __forceinline__ void cpa_wait1() {
    asm volatile("cp.async.wait_group 1;\n" ::: "memory");
}

// ---------------- fp32 -> bf16 conversion ----------------
__global__ void cvt4_kernel(const float4* __restrict__ in,
                            __nv_bfloat162* __restrict__ out, int n4) {
    int i = blockIdx.x * blockDim.x + threadIdx.x;
    int stride = gridDim.x * blockDim.x;
    for (; i < n4; i += stride) {
        float4 v = in[i];
        out[2 * i]     = __floats2bfloat162_rn(v.x, v.y);
        out[2 * i + 1] = __floats2bfloat162_rn(v.z, v.w);
    }
}

// ---------------- projection GEMM (smem-staged, cp.async dbuf) ----------------
// C[4096, F] = Xb[4096,1024] @ Wb[F,1024]^T -> out[b,h,n,e] bf16.
// 256 thr, CTA tile 128x128, k-chunk 32, 8 warps (2x4), warp tile 64x32.
#define PJ_LDS 48   // bf16 stride for 32-col k chunk (96B rows, 32B-multiple)
__global__ __launch_bounds__(256)
void proj_kernel(const bf16* __restrict__ A, const bf16* __restrict__ W,
                 bf16* __restrict__ out, int Dh) {
    extern __shared__ char smem_raw[];
    bf16* sA = (bf16*)smem_raw;                 // [2][128][PJ_LDS]
    bf16* sB = sA + 2 * 128 * PJ_LDS;           // [2][128][PJ_LDS]
    float* patch = (float*)smem_raw;            // epilogue reuse (per warp 16x20)

    int tid  = threadIdx.x;
    int wid  = tid >> 5;
    int lane = tid & 31;
    int warp_m = wid >> 2;          // 0..1
    int warp_f = wid & 3;           // 0..3
    int rowA0 = blockIdx.y * 128;
    int colB0 = blockIdx.x * 128;
    int row0 = rowA0 + warp_m * 64;
    int col0 = colB0 + warp_f * 32;

    wmma::fragment<wmma::accumulator, 16, 16, 16, float> acc[4][2];
    #pragma unroll
    for (int i = 0; i < 4; i++)
        #pragma unroll
        for (int j = 0; j < 2; j++) wmma::fill_fragment(acc[i][j], 0.0f);

    // loader: 128 rows x 32 cols bf16 = 512 chunks of 16B; 2 per thread
    auto issue_chunk = [&](int buf, int k0) {
        #pragma unroll
        for (int p = 0; p < 2; p++) {
            int idx = tid + p * 256;
            int r = idx >> 2, ch = idx & 3;
            cpa16(&sA[(buf * 128 + r) * PJ_LDS + ch * 8],
                  &A[(size_t)(rowA0 + r) * DD + k0 + ch * 8]);
            cpa16(&sB[(buf * 128 + r) * PJ_LDS + ch * 8],
                  &W[(size_t)(colB0 + r) * DD + k0 + ch * 8]);
        }
        cpa_commit();
    };

    issue_chunk(0, 0);
    const int NCH = DD / 32;   // 32 chunks
    for (int kc = 0; kc < NCH; kc++) {
        int cur = kc & 1;
        bool has_next = (kc + 1 < NCH);
        if (has_next) issue_chunk(cur ^ 1, (kc + 1) * 32);
        if (has_next) cpa_wait1(); else cpa_wait0();
        __syncthreads();

        #pragma unroll
        for (int ks = 0; ks < 2; ks++) {
            wmma::fragment<wmma::matrix_a, 16, 16, 16, bf16, wmma::row_major> a[4];
            wmma::fragment<wmma::matrix_b, 16, 16, 16, bf16, wmma::col_major> b[2];
            #pragma unroll
            for (int i = 0; i < 4; i++)
                wmma::load_matrix_sync(a[i],
                    &sA[(cur * 128 + warp_m * 64 + i * 16) * PJ_LDS + ks * 16], PJ_LDS);
            #pragma unroll
            for (int j = 0; j < 2; j++)
                wmma::load_matrix_sync(b[j],
                    &sB[(cur * 128 + warp_f * 32 + j * 16) * PJ_LDS + ks * 16], PJ_LDS);
            #pragma unroll
            for (int i = 0; i < 4; i++)
                #pragma unroll
                for (int j = 0; j < 2; j++)
                    wmma::mma_sync(acc[i][j], a[i], b[j], acc[i][j]);
        }
        __syncthreads();
    }

    // epilogue: remap (row=b*N+n, col=h*Dh+e) -> [b,h,n,e] bf16
    float* mypatch = patch + wid * 16 * 20;
    #pragma unroll
    for (int i = 0; i < 4; i++) {
        #pragma unroll
        for (int j = 0; j < 2; j++) {
            wmma::store_matrix_sync(mypatch, acc[i][j], 20, wmma::mem_row_major);
            __syncwarp();
            for (int t = lane; t < 256; t += 32) {
                int r = t >> 4, c = t & 15;
                int grow = row0 + i * 16 + r;
                int gcol = col0 + j * 16 + c;
                int b_ = grow >> 11;
                int n_ = grow & 2047;
                int h_ = gcol / Dh;
                int e_ = gcol - h_ * Dh;
                out[(((size_t)b_ * HH + h_) * NN + n_) * Dh + e_] =
                    __float2bfloat16(mypatch[r * 20 + c]);
            }
            __syncwarp();
        }
    }
}

// ---------------- fused causal relu-attention ----------------
// Grid (colchunk=8, rowtile=32, b=2), 256 thr (8 warps).
// CTA owns out[b, row0:row0+64, col0:col0+128]; loops all 8 heads and causal
// m-tiles; writes out = x + acc once (no atomics).
#define AT_LDS 144   // bf16 stride (288B rows, 32B-multiple)
#define AT_LDSF 72   // fp32 stride for S (288B)
#define AT_LDSO 136  // fp32 stride for epilogue tile (544B)
__global__ __launch_bounds__(256)
void attn_kernel(const bf16* __restrict__ Qg, const bf16* __restrict__ Kg,
                 const bf16* __restrict__ Vg, const float* __restrict__ x,
                 float* __restrict__ out) {
    extern __shared__ char smem_raw[];
    bf16*  sQ  = (bf16*)smem_raw;                    // [64][AT_LDS]
    bf16*  sK  = sQ + 64 * AT_LDS;                   // [2][64][AT_LDS]
    bf16*  sV  = sK + 2 * 64 * AT_LDS;               // [2][64][AT_LDS]
    float* sS  = (float*)(sV + 2 * 64 * AT_LDS);     // [64][AT_LDSF]
    bf16*  sSb = (bf16*)(sS + 64 * AT_LDSF);         // [64][AT_LDS]
    float* sOut = sS;                                // epilogue reuse [64][AT_LDSO]

    int tid  = threadIdx.x;
    int wid  = tid >> 5;
    int b_   = blockIdx.z;
    int row0 = blockIdx.y * 64;
    int col0 = blockIdx.x * 128;
    int rg   = (wid >> 1) * 16;      // warp row group (same for S and PV phase)
    int cgS  = (wid & 1) * 32;       // S-phase col group
    int cgP  = (wid & 1) * 64;       // PV-phase col group
    const int ntiles = blockIdx.y + 1;
    const float inv_n = 1.0f / (float)NN;

    wmma::fragment<wmma::accumulator, 16, 16, 16, float> oacc[4];
    #pragma unroll
    for (int j = 0; j < 4; j++) wmma::fill_fragment(oacc[j], 0.0f);

    // 16KB tile loader: 64 rows x 128 bf16 = 1024 x 16B chunks; 4/thread
    auto load_tile = [&](bf16* dst, const bf16* src, int src_ld) {
        #pragma unroll
        for (int p = 0; p < 4; p++) {
            int idx = tid + p * 256;
            int r = idx >> 4, ch = idx & 15;
            cpa16(&dst[r * AT_LDS + ch * 8], &src[(size_t)r * src_ld + ch * 8]);
        }
    };

    for (int h = 0; h < HH; h++) {
        size_t bh = (size_t)(b_ * HH + h);
        const bf16* Qp = Qg + bh * NN * DKK + (size_t)row0 * DKK;
        const bf16* Kp = Kg + bh * NN * DKK;
        const bf16* Vp = Vg + bh * NN * DVV + col0;

        // head prologue: Q + K0 + V0 as one group
        load_tile(sQ, Qp, DKK);
        load_tile(sK, Kp, DKK);
        load_tile(sV, Vp, DVV);
        cpa_commit();
        cpa_wait0();
        __syncthreads();

        // per-warp Q fragments (16 rows x 128) from smem
        wmma::fragment<wmma::matrix_a, 16, 16, 16, bf16, wmma::row_major> qf[8];
        #pragma unroll
        for (int k = 0; k < 8; k++)
            wmma::load_matrix_sync(qf[k], &sQ[rg * AT_LDS + k * 16], AT_LDS);

        for (int mt = 0; mt < ntiles; mt++) {
            int cur = mt & 1;
            bool has_next = (mt + 1 < ntiles);
            if (has_next) {
                int m1 = (mt + 1) * 64;
                load_tile(&sK[(cur ^ 1) * 64 * AT_LDS], Kp + (size_t)m1 * DKK, DKK);
                load_tile(&sV[(cur ^ 1) * 64 * AT_LDS], Vp + (size_t)m1 * DVV, DVV);
                cpa_commit();
            }

            // ---- S = Q @ K^T : warp -> rows [rg,rg+16) x cols [cgS,cgS+32) ----
            bf16* sKc = &sK[cur * 64 * AT_LDS];
            wmma::fragment<wmma::accumulator, 16, 16, 16, float> sacc[2];
            #pragma unroll
            for (int j = 0; j < 2; j++) wmma::fill_fragment(sacc[j], 0.0f);
            #pragma unroll
            for (int j = 0; j < 2; j++) {
                #pragma unroll
                for (int k = 0; k < 8; k++) {
                    wmma::fragment<wmma::matrix_b, 16, 16, 16, bf16, wmma::col_major> kf;
                    wmma::load_matrix_sync(kf, &sKc[(cgS + j * 16) * AT_LDS + k * 16], AT_LDS);
                    wmma::mma_sync(sacc[j], qf[k], kf, sacc[j]);
                }
            }
            #pragma unroll
            for (int j = 0; j < 2; j++)
                wmma::store_matrix_sync(&sS[rg * AT_LDSF + cgS + j * 16], sacc[j],
                                        AT_LDSF, wmma::mem_row_major);
            __syncthreads();

            // ---- mask + relu + /N -> bf16 ----
            bool diag = (mt == blockIdx.y);
            for (int t = tid; t < 64 * 64; t += 256) {
                int r = t >> 6, c = t & 63;
                float v = fmaxf(sS[r * AT_LDSF + c], 0.0f) * inv_n;
                if (diag && c > r) v = 0.0f;
                sSb[r * AT_LDS + c] = __float2bfloat16(v);
            }
            __syncthreads();

            // ---- out += Sb @ V : warp -> rows [rg,+16) x cols [cgP,cgP+64) ----
            bf16* sVc = &sV[cur * 64 * AT_LDS];
            wmma::fragment<wmma::matrix_a, 16, 16, 16, bf16, wmma::row_major> af[4];
            #pragma unroll
            for (int k2 = 0; k2 < 4; k2++)
                wmma::load_matrix_sync(af[k2], &sSb[rg * AT_LDS + k2 * 16], AT_LDS);
            #pragma unroll
            for (int j = 0; j < 4; j++) {
                #pragma unroll
                for (int k2 = 0; k2 < 4; k2++) {
                    wmma::fragment<wmma::matrix_b, 16, 16, 16, bf16, wmma::row_major> vf;
                    wmma::load_matrix_sync(vf, &sVc[(k2 * 16) * AT_LDS + cgP + j * 16], AT_LDS);
                    wmma::mma_sync(oacc[j], af[k2], vf, oacc[j]);
                }
            }
            __syncthreads();   // all reads of buf `cur` done before next issue
            if (has_next) cpa_wait0();   // next buf's copies landed (barrier next iter)
            __syncthreads();
        }
    }

    // ---- epilogue: out = x + acc (each output element written exactly once) ----
    #pragma unroll
    for (int j = 0; j < 4; j++)
        wmma::store_matrix_sync(&sOut[rg * AT_LDSO + cgP + j * 16], oacc[j],
                                AT_LDSO, wmma::mem_row_major);
    __syncthreads();
    for (int t = tid; t < 64 * 128; t += 256) {
        int r = t >> 7, c = t & 127;
        size_t gi = ((size_t)(b_ * NN + row0 + r)) * DVV + col0 + c;
        out[gi] = x[gi] + sOut[r * AT_LDSO + c];
    }
}

// ---------------- launch ----------------
extern "C" void kernel_launch(void* const* d_in, const int* in_sizes, int n_in,
                              void* d_out, int out_size) {
    const float* x  = (const float*)d_in[0];
    const float* Wq = (const float*)d_in[1];
    const float* Wk = (const float*)d_in[2];
    const float* Wv = (const float*)d_in[3];
    float* out = (float*)d_out;

    void* p;
    cudaGetSymbolAddress(&p, g_xb); bf16* xb = (bf16*)p;
    cudaGetSymbolAddress(&p, g_wq); bf16* wq = (bf16*)p;
    cudaGetSymbolAddress(&p, g_wk); bf16* wk = (bf16*)p;
    cudaGetSymbolAddress(&p, g_wv); bf16* wv = (bf16*)p;
    cudaGetSymbolAddress(&p, g_Q);  bf16* Q  = (bf16*)p;
    cudaGetSymbolAddress(&p, g_K);  bf16* K  = (bf16*)p;
    cudaGetSymbolAddress(&p, g_V);  bf16* V  = (bf16*)p;

    const int nx  = BB * NN * DD;
    const int nwq = HH * DKK * DD;
    const int nwv = HH * DVV * DD;

    const int proj_smem = 2 * 2 * 128 * PJ_LDS * 2;                 // 49152
    const int attn_smem = (64 * AT_LDS + 4 * 64 * AT_LDS) * 2       // Q,K,V
                        + 64 * AT_LDSF * 4 + 64 * AT_LDS * 2;       // S, Sb
    static bool attr_done = false;
    if (!attr_done) {
        cudaFuncSetAttribute(proj_kernel,
            cudaFuncAttributeMaxDynamicSharedMemorySize, proj_smem);
        cudaFuncSetAttribute(attn_kernel,
            cudaFuncAttributeMaxDynamicSharedMemorySize, attn_smem);
        attr_done = true;
    }

    cvt4_kernel<<<2048, 256>>>((const float4*)x,  (__nv_bfloat162*)xb, nx  / 4);
    cvt4_kernel<<<1024, 256>>>((const float4*)Wq, (__nv_bfloat162*)wq, nwq / 4);
    cvt4_kernel<<<1024, 256>>>((const float4*)Wk, (__nv_bfloat162*)wk, nwq / 4);
    cvt4_kernel<<<2048, 256>>>((const float4*)Wv, (__nv_bfloat162*)wv, nwv / 4);

    proj_kernel<<<dim3(HH * DKK / 128, BB * NN / 128), 256, proj_smem>>>(xb, wq, Q, DKK);
    proj_kernel<<<dim3(HH * DKK / 128, BB * NN / 128), 256, proj_smem>>>(xb, wk, K, DKK);
    proj_kernel<<<dim3(HH * DVV / 128, BB * NN / 128), 256, proj_smem>>>(xb, wv, V, DVV);

    attn_kernel<<<dim3(DVV / 128, NN / 64, BB), 256, attn_smem>>>(Q, K, V, x, out);
}

// round 4
// speedup vs baseline: 3.9152x; 2.2557x over previous
#include <cuda_runtime.h>
#include <cuda_bf16.h>
#include <mma.h>
#include <cstdint>

using namespace nvcuda;
using bf16 = __nv_bfloat16;

#define BB  2
#define NN  2048
#define DD  1024
#define HH  8
#define DKK 128
#define DVV 1024

// ---------------- static scratch (no allocations allowed) ----------------
__device__ bf16 g_xb[BB * NN * DD];
__device__ bf16 g_wq[HH * DKK * DD];
__device__ bf16 g_wk[HH * DKK * DD];
__device__ bf16 g_wv[HH * DVV * DD];
__device__ bf16 g_Q [BB * HH * NN * DKK];
__device__ bf16 g_K [BB * HH * NN * DKK];
__device__ bf16 g_V [BB * HH * NN * DVV];

// ---------------- asm helpers ----------------
__device__ __forceinline__ void cpa16(void* dst_smem, const void* src_gmem) {
    unsigned d = (unsigned)__cvta_generic_to_shared(dst_smem);
    asm volatile("cp.async.cg.shared.global [%0], [%1], 16;\n" :: "r"(d), "l"(src_gmem));
}
__device__ __forceinline__ void cpa_commit() {
    asm volatile("cp.async.commit_group;\n" ::: "memory");
}
__device__ __forceinline__ void cpa_wait0() {
    asm volatile("cp.async.wait_group 0;\n" ::: "memory");
}
__device__ __forceinline__ unsigned sm32(const void* p) {
    return (unsigned)__cvta_generic_to_shared(p);
}
__device__ __forceinline__ void ldsm_x4(unsigned& r0, unsigned& r1, unsigned& r2,
                                        unsigned& r3, unsigned addr) {
    asm volatile("ldmatrix.sync.aligned.m8n8.x4.shared.b16 {%0,%1,%2,%3}, [%4];\n"
                 : "=r"(r0), "=r"(r1), "=r"(r2), "=r"(r3) : "r"(addr));
}
__device__ __forceinline__ void ldsm_x4_t(unsigned& r0, unsigned& r1, unsigned& r2,
                                          unsigned& r3, unsigned addr) {
    asm volatile("ldmatrix.sync.aligned.m8n8.x4.trans.shared.b16 {%0,%1,%2,%3}, [%4];\n"
                 : "=r"(r0), "=r"(r1), "=r"(r2), "=r"(r3) : "r"(addr));
}
__device__ __forceinline__ void mma_bf16(float c[4], const unsigned a[4],
                                         unsigned b0, unsigned b1) {
    asm volatile("mma.sync.aligned.m16n8k16.row.col.f32.bf16.bf16.f32 "
                 "{%0,%1,%2,%3}, {%4,%5,%6,%7}, {%8,%9}, {%0,%1,%2,%3};\n"
                 : "+f"(c[0]), "+f"(c[1]), "+f"(c[2]), "+f"(c[3])
                 : "r"(a[0]), "r"(a[1]), "r"(a[2]), "r"(a[3]), "r"(b0), "r"(b1));
}
__device__ __forceinline__ unsigned pack_bf2(float lo, float hi) {
    unsigned r;
    asm("cvt.rn.bf16x2.f32 %0, %1, %2;\n" : "=r"(r) : "f"(hi), "f"(lo));
    return r;
}

// ---------------- fp32 -> bf16 conversion ----------------
__global__ void cvt4_kernel(const float4* __restrict__ in,
                            __nv_bfloat162* __restrict__ out, int n4) {
    int i = blockIdx.x * blockDim.x + threadIdx.x;
    int stride = gridDim.x * blockDim.x;
    for (; i < n4; i += stride) {
        float4 v = in[i];
        out[2 * i]     = __floats2bfloat162_rn(v.x, v.y);
        out[2 * i + 1] = __floats2bfloat162_rn(v.z, v.w);
    }
}

// ---------------- projection GEMM (1-barrier pipelined) ----------------
#define PJ_LDS 48
__global__ __launch_bounds__(256)
void proj_kernel(const bf16* __restrict__ A, const bf16* __restrict__ W,
                 bf16* __restrict__ out, int Dh) {
    extern __shared__ char smem_raw[];
    bf16* sA = (bf16*)smem_raw;                 // [2][128][PJ_LDS]
    bf16* sB = sA + 2 * 128 * PJ_LDS;           // [2][128][PJ_LDS]
    float* patch = (float*)smem_raw;            // epilogue reuse

    int tid  = threadIdx.x;
    int wid  = tid >> 5;
    int lane = tid & 31;
    int warp_m = wid >> 2;
    int warp_f = wid & 3;
    int rowA0 = blockIdx.y * 128;
    int colB0 = blockIdx.x * 128;
    int row0 = rowA0 + warp_m * 64;
    int col0 = colB0 + warp_f * 32;

    wmma::fragment<wmma::accumulator, 16, 16, 16, float> acc[4][2];
    #pragma unroll
    for (int i = 0; i < 4; i++)
        #pragma unroll
        for (int j = 0; j < 2; j++) wmma::fill_fragment(acc[i][j], 0.0f);

    auto issue_chunk = [&](int buf, int k0) {
        #pragma unroll
        for (int p = 0; p < 2; p++) {
            int idx = tid + p * 256;
            int r = idx >> 2, ch = idx & 3;
            cpa16(&sA[(buf * 128 + r) * PJ_LDS + ch * 8],
                  &A[(size_t)(rowA0 + r) * DD + k0 + ch * 8]);
            cpa16(&sB[(buf * 128 + r) * PJ_LDS + ch * 8],
                  &W[(size_t)(colB0 + r) * DD + k0 + ch * 8]);
        }
        cpa_commit();
    };

    issue_chunk(0, 0);
    const int NCH = DD / 32;
    for (int kc = 0; kc < NCH; kc++) {
        int cur = kc & 1;
        cpa_wait0();
        __syncthreads();
        if (kc + 1 < NCH) issue_chunk(cur ^ 1, (kc + 1) * 32);

        #pragma unroll
        for (int ks = 0; ks < 2; ks++) {
            wmma::fragment<wmma::matrix_a, 16, 16, 16, bf16, wmma::row_major> a[4];
            wmma::fragment<wmma::matrix_b, 16, 16, 16, bf16, wmma::col_major> b[2];
            #pragma unroll
            for (int i = 0; i < 4; i++)
                wmma::load_matrix_sync(a[i],
                    &sA[(cur * 128 + warp_m * 64 + i * 16) * PJ_LDS + ks * 16], PJ_LDS);
            #pragma unroll
            for (int j = 0; j < 2; j++)
                wmma::load_matrix_sync(b[j],
                    &sB[(cur * 128 + warp_f * 32 + j * 16) * PJ_LDS + ks * 16], PJ_LDS);
            #pragma unroll
            for (int i = 0; i < 4; i++)
                #pragma unroll
                for (int j = 0; j < 2; j++)
                    wmma::mma_sync(acc[i][j], a[i], b[j], acc[i][j]);
        }
    }
    __syncthreads();

    float* mypatch = patch + wid * 16 * 20;
    #pragma unroll
    for (int i = 0; i < 4; i++) {
        #pragma unroll
        for (int j = 0; j < 2; j++) {
            wmma::store_matrix_sync(mypatch, acc[i][j], 20, wmma::mem_row_major);
            __syncwarp();
            for (int t = lane; t < 256; t += 32) {
                int r = t >> 4, c = t & 15;
                int grow = row0 + i * 16 + r;
                int gcol = col0 + j * 16 + c;
                int b_ = grow >> 11;
                int n_ = grow & 2047;
                int h_ = gcol / Dh;
                int e_ = gcol - h_ * Dh;
                out[(((size_t)b_ * HH + h_) * NN + n_) * Dh + e_] =
                    __float2bfloat16(mypatch[r * 20 + c]);
            }
            __syncwarp();
        }
    }
}

// ---------------- FA2-style fused causal relu-attention ----------------
// Grid (colchunk=4, rowtile=32 reversed, b=2), 256 thr (8 warps).
// Warp w: rows [rg,rg+16), PV cols [ch,ch+128). S kept in registers:
// relu/mask/scale in-reg, packed to bf16 A-frags, PV via mma.m16n8k16.
#define QLDS 136   // bf16 row stride for Q/K tiles (272B)
#define VLDS 264   // bf16 row stride for V tiles (528B)
__global__ __launch_bounds__(256, 1)
void attn_kernel(const bf16* __restrict__ Qg, const bf16* __restrict__ Kg,
                 const bf16* __restrict__ Vg, const float* __restrict__ x,
                 float* __restrict__ out) {
    extern __shared__ char smem_raw[];
    bf16* sQ = (bf16*)smem_raw;          // [2][64][QLDS]
    bf16* sK = sQ + 2 * 64 * QLDS;       // [2][64][QLDS]
    bf16* sV = sK + 2 * 64 * QLDS;       // [2][64][VLDS]

    int tid  = threadIdx.x;
    int lane = tid & 31;
    int wid  = tid >> 5;
    int b_   = blockIdx.z;
    int rowtile = gridDim.y - 1 - blockIdx.y;   // heavy tiles first
    int row0 = rowtile * 64;
    int col0 = blockIdx.x * 256;
    int rg   = (wid >> 1) * 16;
    int ch   = (wid & 1) * 128;
    int ntiles = rowtile + 1;
    int gID = lane >> 2, tig = lane & 3;
    int lsub = lane >> 3, lr = lane & 7;
    const float inv_n = 1.0f / (float)NN;

    float oacc[16][4];
    #pragma unroll
    for (int i = 0; i < 16; i++)
        #pragma unroll
        for (int j = 0; j < 4; j++) oacc[i][j] = 0.0f;

    // loaders: K/Q tile 64x128 (4 chunks/thr), V tile 64x256 (8 chunks/thr)
    auto loadQK = [&](bf16* dst, const bf16* src) {
        #pragma unroll
        for (int p = 0; p < 4; p++) {
            int idx = tid + p * 256;
            int r = idx >> 4, c = idx & 15;
            cpa16(&dst[r * QLDS + c * 8], &src[(size_t)r * DKK + c * 8]);
        }
    };
    auto loadV = [&](bf16* dst, const bf16* src) {
        #pragma unroll
        for (int p = 0; p < 8; p++) {
            int idx = tid + p * 256;
            int r = idx >> 5, c = idx & 31;
            cpa16(&dst[r * VLDS + c * 8], &src[(size_t)r * DVV + c * 8]);
        }
    };

    size_t bh0 = (size_t)b_ * HH;
    // prologue: head 0 Q,K0,V0 -> buf 0
    loadQK(sQ, Qg + bh0 * NN * DKK + (size_t)row0 * DKK);
    loadQK(sK, Kg + bh0 * NN * DKK);
    loadV (sV, Vg + bh0 * NN * DVV + col0);
    cpa_commit();

    unsigned qa[8][4];
    int p = 0;

    for (int h = 0; h < HH; h++) {
        size_t bh = bh0 + h;
        const bf16* Kp = Kg + bh * NN * DKK;
        const bf16* Vp = Vg + bh * NN * DVV + col0;

        for (int mt = 0; mt < ntiles; mt++) {
            cpa_wait0();
            __syncthreads();

            if (mt == 0) {
                // load Q A-frags for this head from sQ[h&1]
                bf16* sQh = sQ + (h & 1) * 64 * QLDS;
                int qrow = rg + (lsub & 1) * 8 + lr;
                #pragma unroll
                for (int k = 0; k < 8; k++) {
                    unsigned addr = sm32(&sQh[qrow * QLDS + k * 16 + (lsub >> 1) * 8]);
                    ldsm_x4(qa[k][0], qa[k][1], qa[k][2], qa[k][3], addr);
                }
            }

            // prefetch next tile / next head
            if (mt + 1 < ntiles) {
                loadQK(sK + (p ^ 1) * 64 * QLDS, Kp + (size_t)(mt + 1) * 64 * DKK);
                loadV (sV + (p ^ 1) * 64 * VLDS, Vp + (size_t)(mt + 1) * 64 * DVV);
                cpa_commit();
            } else if (h + 1 < HH) {
                loadQK(sQ + ((h + 1) & 1) * 64 * QLDS,
                       Qg + (bh + 1) * NN * DKK + (size_t)row0 * DKK);
                loadQK(sK + (p ^ 1) * 64 * QLDS, Kg + (bh + 1) * NN * DKK);
                loadV (sV + (p ^ 1) * 64 * VLDS, Vg + (bh + 1) * NN * DVV + col0);
                cpa_commit();
            }

            // ---- S = Q @ K^T (16 rows x 64 keys per warp, in registers) ----
            bf16* sKc = sK + p * 64 * QLDS;
            float sc[8][4];
            #pragma unroll
            for (int j = 0; j < 8; j++)
                #pragma unroll
                for (int i = 0; i < 4; i++) sc[j][i] = 0.0f;

            #pragma unroll
            for (int j = 0; j < 8; j++) {
                #pragma unroll
                for (int kp = 0; kp < 4; kp++) {
                    unsigned kb0, kb1, kb2, kb3;
                    unsigned addr = sm32(&sKc[(j * 8 + lr) * QLDS + kp * 32 + lsub * 8]);
                    ldsm_x4(kb0, kb1, kb2, kb3, addr);
                    mma_bf16(sc[j], qa[2 * kp],     kb0, kb1);
                    mma_bf16(sc[j], qa[2 * kp + 1], kb2, kb3);
                }
            }

            // ---- relu + causal mask + /N in-reg, pack to bf16 A-frags ----
            int m0 = mt * 64;
            int rowa = row0 + rg + gID;
            int rowb = rowa + 8;
            bool diag = (mt == rowtile);
            unsigned sa[4][4];
            #pragma unroll
            for (int j = 0; j < 8; j++) {
                int cb = m0 + j * 8 + 2 * tig;
                float v0 = fmaxf(sc[j][0], 0.0f) * inv_n;
                float v1 = fmaxf(sc[j][1], 0.0f) * inv_n;
                float v2 = fmaxf(sc[j][2], 0.0f) * inv_n;
                float v3 = fmaxf(sc[j][3], 0.0f) * inv_n;
                if (diag) {
                    if (cb     > rowa) v0 = 0.0f;
                    if (cb + 1 > rowa) v1 = 0.0f;
                    if (cb     > rowb) v2 = 0.0f;
                    if (cb + 1 > rowb) v3 = 0.0f;
                }
                sa[j >> 1][(j & 1) * 2 + 0] = pack_bf2(v0, v1);
                sa[j >> 1][(j & 1) * 2 + 1] = pack_bf2(v2, v3);
            }

            // ---- out += S @ V (16 rows x 128 cols per warp) ----
            bf16* sVc = sV + p * 64 * VLDS;
            int vrow = (lsub & 1) * 8 + lr;
            int vcol = ch + (lsub >> 1) * 8;
            #pragma unroll
            for (int kt = 0; kt < 4; kt++) {
                #pragma unroll
                for (int np = 0; np < 8; np++) {
                    unsigned v0, v1, v2, v3;
                    unsigned addr = sm32(&sVc[(kt * 16 + vrow) * VLDS + vcol + np * 16]);
                    ldsm_x4_t(v0, v1, v2, v3, addr);
                    mma_bf16(oacc[np * 2],     sa[kt], v0, v1);
                    mma_bf16(oacc[np * 2 + 1], sa[kt], v2, v3);
                }
            }
            p ^= 1;
        }
    }

    // ---- epilogue: out = x + acc, coords known per lane ----
    #pragma unroll
    for (int nt = 0; nt < 16; nt++) {
        int col = col0 + ch + nt * 8 + 2 * tig;
        size_t g0 = ((size_t)(b_ * NN + row0 + rg + gID)) * DVV + col;
        size_t g1 = g0 + (size_t)8 * DVV;
        float2 xa = *(const float2*)(x + g0);
        float2 xb = *(const float2*)(x + g1);
        float2 ra = {xa.x + oacc[nt][0], xa.y + oacc[nt][1]};
        float2 rb = {xb.x + oacc[nt][2], xb.y + oacc[nt][3]};
        *(float2*)(out + g0) = ra;
        *(float2*)(out + g1) = rb;
    }
}

// ---------------- launch ----------------
extern "C" void kernel_launch(void* const* d_in, const int* in_sizes, int n_in,
                              void* d_out, int out_size) {
    const float* x  = (const float*)d_in[0];
    const float* Wq = (const float*)d_in[1];
    const float* Wk = (const float*)d_in[2];
    const float* Wv = (const float*)d_in[3];
    float* out = (float*)d_out;

    void* p;
    cudaGetSymbolAddress(&p, g_xb); bf16* xb = (bf16*)p;
    cudaGetSymbolAddress(&p, g_wq); bf16* wq = (bf16*)p;
    cudaGetSymbolAddress(&p, g_wk); bf16* wk = (bf16*)p;
    cudaGetSymbolAddress(&p, g_wv); bf16* wv = (bf16*)p;
    cudaGetSymbolAddress(&p, g_Q);  bf16* Q  = (bf16*)p;
    cudaGetSymbolAddress(&p, g_K);  bf16* K  = (bf16*)p;
    cudaGetSymbolAddress(&p, g_V);  bf16* V  = (bf16*)p;

    const int nx  = BB * NN * DD;
    const int nwq = HH * DKK * DD;
    const int nwv = HH * DVV * DD;

    const int proj_smem = 2 * 2 * 128 * PJ_LDS * 2;                       // 49152
    const int attn_smem = (2 * 64 * QLDS * 2 + 2 * 64 * VLDS) * 2;        // 137216
    static bool attr_done = false;
    if (!attr_done) {
        cudaFuncSetAttribute(proj_kernel,
            cudaFuncAttributeMaxDynamicSharedMemorySize, proj_smem);
        cudaFuncSetAttribute(attn_kernel,
            cudaFuncAttributeMaxDynamicSharedMemorySize, attn_smem);
        attr_done = true;
    }

    cvt4_kernel<<<2048, 256>>>((const float4*)x,  (__nv_bfloat162*)xb, nx  / 4);
    cvt4_kernel<<<1024, 256>>>((const float4*)Wq, (__nv_bfloat162*)wq, nwq / 4);
    cvt4_kernel<<<1024, 256>>>((const float4*)Wk, (__nv_bfloat162*)wk, nwq / 4);
    cvt4_kernel<<<2048, 256>>>((const float4*)Wv, (__nv_bfloat162*)wv, nwv / 4);

    proj_kernel<<<dim3(HH * DKK / 128, BB * NN / 128), 256, proj_smem>>>(xb, wq, Q, DKK);
    proj_kernel<<<dim3(HH * DKK / 128, BB * NN / 128), 256, proj_smem>>>(xb, wk, K, DKK);
    proj_kernel<<<dim3(HH * DVV / 128, BB * NN / 128), 256, proj_smem>>>(xb, wv, V, DVV);

    attn_kernel<<<dim3(DVV / 256, NN / 64, BB), 256, attn_smem>>>(Q, K, V, x, out);
}

// round 5
// speedup vs baseline: 3.9157x; 1.0001x over previous
#include <cuda_runtime.h>
#include <cuda_bf16.h>
#include <mma.h>
#include <cstdint>

using namespace nvcuda;
using bf16 = __nv_bfloat16;

#define BB  2
#define NN  2048
#define DD  1024
#define HH  8
#define DKK 128
#define DVV 1024

// ---------------- static scratch (no allocations allowed) ----------------
__device__ bf16 g_xb[BB * NN * DD];
__device__ bf16 g_wq[HH * DKK * DD];
__device__ bf16 g_wk[HH * DKK * DD];
__device__ bf16 g_wv[HH * DVV * DD];
__device__ bf16 g_Q [BB * HH * NN * DKK];
__device__ bf16 g_K [BB * HH * NN * DKK];
__device__ bf16 g_V [BB * HH * NN * DVV];

// ---------------- asm helpers ----------------
__device__ __forceinline__ void cpa16(void* dst_smem, const void* src_gmem) {
    unsigned d = (unsigned)__cvta_generic_to_shared(dst_smem);
    asm volatile("cp.async.cg.shared.global [%0], [%1], 16;\n" :: "r"(d), "l"(src_gmem));
}
__device__ __forceinline__ void cpa_commit() {
    asm volatile("cp.async.commit_group;\n" ::: "memory");
}
__device__ __forceinline__ void cpa_wait0() {
    asm volatile("cp.async.wait_group 0;\n" ::: "memory");
}
__device__ __forceinline__ unsigned sm32(const void* p) {
    return (unsigned)__cvta_generic_to_shared(p);
}
__device__ __forceinline__ void ldsm_x4(unsigned& r0, unsigned& r1, unsigned& r2,
                                        unsigned& r3, unsigned addr) {
    asm volatile("ldmatrix.sync.aligned.m8n8.x4.shared.b16 {%0,%1,%2,%3}, [%4];\n"
                 : "=r"(r0), "=r"(r1), "=r"(r2), "=r"(r3) : "r"(addr));
}
__device__ __forceinline__ void ldsm_x4_t(unsigned& r0, unsigned& r1, unsigned& r2,
                                          unsigned& r3, unsigned addr) {
    asm volatile("ldmatrix.sync.aligned.m8n8.x4.trans.shared.b16 {%0,%1,%2,%3}, [%4];\n"
                 : "=r"(r0), "=r"(r1), "=r"(r2), "=r"(r3) : "r"(addr));
}
__device__ __forceinline__ void mma_bf16(float c[4], const unsigned a[4],
                                         unsigned b0, unsigned b1) {
    asm volatile("mma.sync.aligned.m16n8k16.row.col.f32.bf16.bf16.f32 "
                 "{%0,%1,%2,%3}, {%4,%5,%6,%7}, {%8,%9}, {%0,%1,%2,%3};\n"
                 : "+f"(c[0]), "+f"(c[1]), "+f"(c[2]), "+f"(c[3])
                 : "r"(a[0]), "r"(a[1]), "r"(a[2]), "r"(a[3]), "r"(b0), "r"(b1));
}
__device__ __forceinline__ unsigned pack_bf2(float lo, float hi) {
    unsigned r;
    asm("cvt.rn.bf16x2.f32 %0, %1, %2;\n" : "=r"(r) : "f"(hi), "f"(lo));
    return r;
}

// ---------------- fp32 -> bf16 conversion ----------------
__global__ void cvt4_kernel(const float4* __restrict__ in,
                            __nv_bfloat162* __restrict__ out, int n4) {
    int i = blockIdx.x * blockDim.x + threadIdx.x;
    int stride = gridDim.x * blockDim.x;
    for (; i < n4; i += stride) {
        float4 v = in[i];
        out[2 * i]     = __floats2bfloat162_rn(v.x, v.y);
        out[2 * i + 1] = __floats2bfloat162_rn(v.z, v.w);
    }
}

// ---------------- projection GEMM (1-barrier pipelined) ----------------
#define PJ_LDS 48
__global__ __launch_bounds__(256)
void proj_kernel(const bf16* __restrict__ A, const bf16* __restrict__ W,
                 bf16* __restrict__ out, int Dh) {
    extern __shared__ char smem_raw[];
    bf16* sA = (bf16*)smem_raw;                 // [2][128][PJ_LDS]
    bf16* sB = sA + 2 * 128 * PJ_LDS;           // [2][128][PJ_LDS]
    float* patch = (float*)smem_raw;            // epilogue reuse

    int tid  = threadIdx.x;
    int wid  = tid >> 5;
    int lane = tid & 31;
    int warp_m = wid >> 2;
    int warp_f = wid & 3;
    int rowA0 = blockIdx.y * 128;
    int colB0 = blockIdx.x * 128;
    int row0 = rowA0 + warp_m * 64;
    int col0 = colB0 + warp_f * 32;

    wmma::fragment<wmma::accumulator, 16, 16, 16, float> acc[4][2];
    #pragma unroll
    for (int i = 0; i < 4; i++)
        #pragma unroll
        for (int j = 0; j < 2; j++) wmma::fill_fragment(acc[i][j], 0.0f);

    auto issue_chunk = [&](int buf, int k0) {
        #pragma unroll
        for (int p = 0; p < 2; p++) {
            int idx = tid + p * 256;
            int r = idx >> 2, ch = idx & 3;
            cpa16(&sA[(buf * 128 + r) * PJ_LDS + ch * 8],
                  &A[(size_t)(rowA0 + r) * DD + k0 + ch * 8]);
            cpa16(&sB[(buf * 128 + r) * PJ_LDS + ch * 8],
                  &W[(size_t)(colB0 + r) * DD + k0 + ch * 8]);
        }
        cpa_commit();
    };

    issue_chunk(0, 0);
    const int NCH = DD / 32;
    for (int kc = 0; kc < NCH; kc++) {
        int cur = kc & 1;
        cpa_wait0();
        __syncthreads();
        if (kc + 1 < NCH) issue_chunk(cur ^ 1, (kc + 1) * 32);

        #pragma unroll
        for (int ks = 0; ks < 2; ks++) {
            wmma::fragment<wmma::matrix_a, 16, 16, 16, bf16, wmma::row_major> a[4];
            wmma::fragment<wmma::matrix_b, 16, 16, 16, bf16, wmma::col_major> b[2];
            #pragma unroll
            for (int i = 0; i < 4; i++)
                wmma::load_matrix_sync(a[i],
                    &sA[(cur * 128 + warp_m * 64 + i * 16) * PJ_LDS + ks * 16], PJ_LDS);
            #pragma unroll
            for (int j = 0; j < 2; j++)
                wmma::load_matrix_sync(b[j],
                    &sB[(cur * 128 + warp_f * 32 + j * 16) * PJ_LDS + ks * 16], PJ_LDS);
            #pragma unroll
            for (int i = 0; i < 4; i++)
                #pragma unroll
                for (int j = 0; j < 2; j++)
                    wmma::mma_sync(acc[i][j], a[i], b[j], acc[i][j]);
        }
    }
    __syncthreads();

    float* mypatch = patch + wid * 16 * 20;
    #pragma unroll
    for (int i = 0; i < 4; i++) {
        #pragma unroll
        for (int j = 0; j < 2; j++) {
            wmma::store_matrix_sync(mypatch, acc[i][j], 20, wmma::mem_row_major);
            __syncwarp();
            for (int t = lane; t < 256; t += 32) {
                int r = t >> 4, c = t & 15;
                int grow = row0 + i * 16 + r;
                int gcol = col0 + j * 16 + c;
                int b_ = grow >> 11;
                int n_ = grow & 2047;
                int h_ = gcol / Dh;
                int e_ = gcol - h_ * Dh;
                out[(((size_t)b_ * HH + h_) * NN + n_) * Dh + e_] =
                    __float2bfloat16(mypatch[r * 20 + c]);
            }
            __syncwarp();
        }
    }
}

// ---------------- FA2-style fused causal relu-attention ----------------
// Grid (colchunk=4, rowtile=32 reversed, b=2), 256 thr (8 warps).
// Warp w: rows [rg,rg+16), PV cols [ch,ch+128). S kept in registers:
// relu/mask/scale in-reg, packed to bf16 A-frags, PV via mma.m16n8k16.
#define QLDS 136   // bf16 row stride for Q/K tiles (272B)
#define VLDS 264   // bf16 row stride for V tiles (528B)
__global__ __launch_bounds__(256, 1)
void attn_kernel(const bf16* __restrict__ Qg, const bf16* __restrict__ Kg,
                 const bf16* __restrict__ Vg, const float* __restrict__ x,
                 float* __restrict__ out) {
    extern __shared__ char smem_raw[];
    bf16* sQ = (bf16*)smem_raw;          // [2][64][QLDS]
    bf16* sK = sQ + 2 * 64 * QLDS;       // [2][64][QLDS]
    bf16* sV = sK + 2 * 64 * QLDS;       // [2][64][VLDS]

    int tid  = threadIdx.x;
    int lane = tid & 31;
    int wid  = tid >> 5;
    int b_   = blockIdx.z;
    int rowtile = gridDim.y - 1 - blockIdx.y;   // heavy tiles first
    int row0 = rowtile * 64;
    int col0 = blockIdx.x * 256;
    int rg   = (wid >> 1) * 16;
    int ch   = (wid & 1) * 128;
    int ntiles = rowtile + 1;
    int gID = lane >> 2, tig = lane & 3;
    int lsub = lane >> 3, lr = lane & 7;
    const float inv_n = 1.0f / (float)NN;

    float oacc[16][4];
    #pragma unroll
    for (int i = 0; i < 16; i++)
        #pragma unroll
        for (int j = 0; j < 4; j++) oacc[i][j] = 0.0f;

    // loaders: K/Q tile 64x128 (4 chunks/thr), V tile 64x256 (8 chunks/thr)
    auto loadQK = [&](bf16* dst, const bf16* src) {
        #pragma unroll
        for (int p = 0; p < 4; p++) {
            int idx = tid + p * 256;
            int r = idx >> 4, c = idx & 15;
            cpa16(&dst[r * QLDS + c * 8], &src[(size_t)r * DKK + c * 8]);
        }
    };
    auto loadV = [&](bf16* dst, const bf16* src) {
        #pragma unroll
        for (int p = 0; p < 8; p++) {
            int idx = tid + p * 256;
            int r = idx >> 5, c = idx & 31;
            cpa16(&dst[r * VLDS + c * 8], &src[(size_t)r * DVV + c * 8]);
        }
    };

    size_t bh0 = (size_t)b_ * HH;
    // prologue: head 0 Q,K0,V0 -> buf 0
    loadQK(sQ, Qg + bh0 * NN * DKK + (size_t)row0 * DKK);
    loadQK(sK, Kg + bh0 * NN * DKK);
    loadV (sV, Vg + bh0 * NN * DVV + col0);
    cpa_commit();

    unsigned qa[8][4];
    int p = 0;

    for (int h = 0; h < HH; h++) {
        size_t bh = bh0 + h;
        const bf16* Kp = Kg + bh * NN * DKK;
        const bf16* Vp = Vg + bh * NN * DVV + col0;

        for (int mt = 0; mt < ntiles; mt++) {
            cpa_wait0();
            __syncthreads();

            if (mt == 0) {
                // load Q A-frags for this head from sQ[h&1]
                bf16* sQh = sQ + (h & 1) * 64 * QLDS;
                int qrow = rg + (lsub & 1) * 8 + lr;
                #pragma unroll
                for (int k = 0; k < 8; k++) {
                    unsigned addr = sm32(&sQh[qrow * QLDS + k * 16 + (lsub >> 1) * 8]);
                    ldsm_x4(qa[k][0], qa[k][1], qa[k][2], qa[k][3], addr);
                }
            }

            // prefetch next tile / next head
            if (mt + 1 < ntiles) {
                loadQK(sK + (p ^ 1) * 64 * QLDS, Kp + (size_t)(mt + 1) * 64 * DKK);
                loadV (sV + (p ^ 1) * 64 * VLDS, Vp + (size_t)(mt + 1) * 64 * DVV);
                cpa_commit();
            } else if (h + 1 < HH) {
                loadQK(sQ + ((h + 1) & 1) * 64 * QLDS,
                       Qg + (bh + 1) * NN * DKK + (size_t)row0 * DKK);
                loadQK(sK + (p ^ 1) * 64 * QLDS, Kg + (bh + 1) * NN * DKK);
                loadV (sV + (p ^ 1) * 64 * VLDS, Vg + (bh + 1) * NN * DVV + col0);
                cpa_commit();
            }

            // ---- S = Q @ K^T (16 rows x 64 keys per warp, in registers) ----
            bf16* sKc = sK + p * 64 * QLDS;
            float sc[8][4];
            #pragma unroll
            for (int j = 0; j < 8; j++)
                #pragma unroll
                for (int i = 0; i < 4; i++) sc[j][i] = 0.0f;

            #pragma unroll
            for (int j = 0; j < 8; j++) {
                #pragma unroll
                for (int kp = 0; kp < 4; kp++) {
                    unsigned kb0, kb1, kb2, kb3;
                    unsigned addr = sm32(&sKc[(j * 8 + lr) * QLDS + kp * 32 + lsub * 8]);
                    ldsm_x4(kb0, kb1, kb2, kb3, addr);
                    mma_bf16(sc[j], qa[2 * kp],     kb0, kb1);
                    mma_bf16(sc[j], qa[2 * kp + 1], kb2, kb3);
                }
            }

            // ---- relu + causal mask + /N in-reg, pack to bf16 A-frags ----
            int m0 = mt * 64;
            int rowa = row0 + rg + gID;
            int rowb = rowa + 8;
            bool diag = (mt == rowtile);
            unsigned sa[4][4];
            #pragma unroll
            for (int j = 0; j < 8; j++) {
                int cb = m0 + j * 8 + 2 * tig;
                float v0 = fmaxf(sc[j][0], 0.0f) * inv_n;
                float v1 = fmaxf(sc[j][1], 0.0f) * inv_n;
                float v2 = fmaxf(sc[j][2], 0.0f) * inv_n;
                float v3 = fmaxf(sc[j][3], 0.0f) * inv_n;
                if (diag) {
                    if (cb     > rowa) v0 = 0.0f;
                    if (cb + 1 > rowa) v1 = 0.0f;
                    if (cb     > rowb) v2 = 0.0f;
                    if (cb + 1 > rowb) v3 = 0.0f;
                }
                sa[j >> 1][(j & 1) * 2 + 0] = pack_bf2(v0, v1);
                sa[j >> 1][(j & 1) * 2 + 1] = pack_bf2(v2, v3);
            }

            // ---- out += S @ V (16 rows x 128 cols per warp) ----
            bf16* sVc = sV + p * 64 * VLDS;
            int vrow = (lsub & 1) * 8 + lr;
            int vcol = ch + (lsub >> 1) * 8;
            #pragma unroll
            for (int kt = 0; kt < 4; kt++) {
                #pragma unroll
                for (int np = 0; np < 8; np++) {
                    unsigned v0, v1, v2, v3;
                    unsigned addr = sm32(&sVc[(kt * 16 + vrow) * VLDS + vcol + np * 16]);
                    ldsm_x4_t(v0, v1, v2, v3, addr);
                    mma_bf16(oacc[np * 2],     sa[kt], v0, v1);
                    mma_bf16(oacc[np * 2 + 1], sa[kt], v2, v3);
                }
            }
            p ^= 1;
        }
    }

    // ---- epilogue: out = x + acc, coords known per lane ----
    #pragma unroll
    for (int nt = 0; nt < 16; nt++) {
        int col = col0 + ch + nt * 8 + 2 * tig;
        size_t g0 = ((size_t)(b_ * NN + row0 + rg + gID)) * DVV + col;
        size_t g1 = g0 + (size_t)8 * DVV;
        float2 xa = *(const float2*)(x + g0);
        float2 xb = *(const float2*)(x + g1);
        float2 ra = {xa.x + oacc[nt][0], xa.y + oacc[nt][1]};
        float2 rb = {xb.x + oacc[nt][2], xb.y + oacc[nt][3]};
        *(float2*)(out + g0) = ra;
        *(float2*)(out + g1) = rb;
    }
}

// ---------------- launch ----------------
extern "C" void kernel_launch(void* const* d_in, const int* in_sizes, int n_in,
                              void* d_out, int out_size) {
    const float* x  = (const float*)d_in[0];
    const float* Wq = (const float*)d_in[1];
    const float* Wk = (const float*)d_in[2];
    const float* Wv = (const float*)d_in[3];
    float* out = (float*)d_out;

    void* p;
    cudaGetSymbolAddress(&p, g_xb); bf16* xb = (bf16*)p;
    cudaGetSymbolAddress(&p, g_wq); bf16* wq = (bf16*)p;
    cudaGetSymbolAddress(&p, g_wk); bf16* wk = (bf16*)p;
    cudaGetSymbolAddress(&p, g_wv); bf16* wv = (bf16*)p;
    cudaGetSymbolAddress(&p, g_Q);  bf16* Q  = (bf16*)p;
    cudaGetSymbolAddress(&p, g_K);  bf16* K  = (bf16*)p;
    cudaGetSymbolAddress(&p, g_V);  bf16* V  = (bf16*)p;

    const int nx  = BB * NN * DD;
    const int nwq = HH * DKK * DD;
    const int nwv = HH * DVV * DD;

    const int proj_smem = 2 * 2 * 128 * PJ_LDS * 2;                       // 49152
    const int attn_smem = (2 * 64 * QLDS * 2 + 2 * 64 * VLDS) * 2;        // 137216
    static bool attr_done = false;
    if (!attr_done) {
        cudaFuncSetAttribute(proj_kernel,
            cudaFuncAttributeMaxDynamicSharedMemorySize, proj_smem);
        cudaFuncSetAttribute(attn_kernel,
            cudaFuncAttributeMaxDynamicSharedMemorySize, attn_smem);
        attr_done = true;
    }

    cvt4_kernel<<<2048, 256>>>((const float4*)x,  (__nv_bfloat162*)xb, nx  / 4);
    cvt4_kernel<<<1024, 256>>>((const float4*)Wq, (__nv_bfloat162*)wq, nwq / 4);
    cvt4_kernel<<<1024, 256>>>((const float4*)Wk, (__nv_bfloat162*)wk, nwq / 4);
    cvt4_kernel<<<2048, 256>>>((const float4*)Wv, (__nv_bfloat162*)wv, nwv / 4);

    proj_kernel<<<dim3(HH * DKK / 128, BB * NN / 128), 256, proj_smem>>>(xb, wq, Q, DKK);
    proj_kernel<<<dim3(HH * DKK / 128, BB * NN / 128), 256, proj_smem>>>(xb, wk, K, DKK);
    proj_kernel<<<dim3(HH * DVV / 128, BB * NN / 128), 256, proj_smem>>>(xb, wv, V, DVV);

    attn_kernel<<<dim3(DVV / 256, NN / 64, BB), 256, attn_smem>>>(Q, K, V, x, out);
}

// round 8
// speedup vs baseline: 4.5896x; 1.1721x over previous
#include <cuda_runtime.h>
#include <cuda_bf16.h>
#include <cstdint>

using bf16 = __nv_bfloat16;

#define BB  2
#define NN  2048
#define DD  1024
#define HH  8
#define DKK 128
#define DVV 1024

// ---------------- static scratch (no allocations allowed) ----------------
__device__ bf16 g_xb[BB * NN * DD];
__device__ bf16 g_wq[HH * DKK * DD];
__device__ bf16 g_wk[HH * DKK * DD];
__device__ bf16 g_wv[HH * DVV * DD];
__device__ bf16 g_Q [BB * HH * NN * DKK];
__device__ bf16 g_K [BB * HH * NN * DKK];
__device__ bf16 g_V [BB * HH * NN * DVV];

// ---------------- asm helpers ----------------
__device__ __forceinline__ void cpa16(void* dst_smem, const void* src_gmem) {
    unsigned d = (unsigned)__cvta_generic_to_shared(dst_smem);
    asm volatile("cp.async.cg.shared.global [%0], [%1], 16;\n" :: "r"(d), "l"(src_gmem));
}
__device__ __forceinline__ void cpa_commit() {
    asm volatile("cp.async.commit_group;\n" ::: "memory");
}
__device__ __forceinline__ void cpa_wait0() {
    asm volatile("cp.async.wait_group 0;\n" ::: "memory");
}
__device__ __forceinline__ unsigned sm32(const void* p) {
    return (unsigned)__cvta_generic_to_shared(p);
}
__device__ __forceinline__ void ldsm_x4(unsigned& r0, unsigned& r1, unsigned& r2,
                                        unsigned& r3, unsigned addr) {
    asm volatile("ldmatrix.sync.aligned.m8n8.x4.shared.b16 {%0,%1,%2,%3}, [%4];\n"
                 : "=r"(r0), "=r"(r1), "=r"(r2), "=r"(r3) : "r"(addr));
}
__device__ __forceinline__ void ldsm_x4_t(unsigned& r0, unsigned& r1, unsigned& r2,
                                          unsigned& r3, unsigned addr) {
    asm volatile("ldmatrix.sync.aligned.m8n8.x4.trans.shared.b16 {%0,%1,%2,%3}, [%4];\n"
                 : "=r"(r0), "=r"(r1), "=r"(r2), "=r"(r3) : "r"(addr));
}
__device__ __forceinline__ void mma_bf16(float c[4], const unsigned a[4],
                                         unsigned b0, unsigned b1) {
    asm volatile("mma.sync.aligned.m16n8k16.row.col.f32.bf16.bf16.f32 "
                 "{%0,%1,%2,%3}, {%4,%5,%6,%7}, {%8,%9}, {%0,%1,%2,%3};\n"
                 : "+f"(c[0]), "+f"(c[1]), "+f"(c[2]), "+f"(c[3])
                 : "r"(a[0]), "r"(a[1]), "r"(a[2]), "r"(a[3]), "r"(b0), "r"(b1));
}
__device__ __forceinline__ unsigned pack_bf2(float lo, float hi) {
    unsigned r;
    asm("cvt.rn.bf16x2.f32 %0, %1, %2;\n" : "=r"(r) : "f"(hi), "f"(lo));
    return r;
}

// ---------------- fused fp32 -> bf16 conversion (all 4 tensors) ----------------
__global__ void cvt_all_kernel(const float4* __restrict__ x,  __nv_bfloat162* __restrict__ xb,
                               const float4* __restrict__ wq, __nv_bfloat162* __restrict__ wqb,
                               const float4* __restrict__ wk, __nv_bfloat162* __restrict__ wkb,
                               const float4* __restrict__ wv, __nv_bfloat162* __restrict__ wvb) {
    const int n0 = BB * NN * DD / 4;          // x
    const int n1 = HH * DKK * DD / 4;         // wq / wk
    const int n2 = HH * DVV * DD / 4;         // wv
    const int total = n0 + 2 * n1 + n2;
    int i = blockIdx.x * blockDim.x + threadIdx.x;
    int stride = gridDim.x * blockDim.x;
    for (; i < total; i += stride) {
        const float4* src;
        __nv_bfloat162* dst;
        int j = i;
        if (j < n0) { src = x; dst = xb; }
        else if ((j -= n0) < n1) { src = wq; dst = wqb; }
        else if ((j -= n1) < n1) { src = wk; dst = wkb; }
        else { j -= n1; src = wv; dst = wvb; }
        float4 v = src[j];
        dst[2 * j]     = __floats2bfloat162_rn(v.x, v.y);
        dst[2 * j + 1] = __floats2bfloat162_rn(v.z, v.w);
    }
}

// ---------------- projection GEMM (ldsm + mma.sync, 1-barrier pipeline) ----------------
// C[4096, Fout] = Xb[4096,1024] @ W[Fout,1024]^T -> out[b,h,n,e] bf16.
// CTA 128x128, k-chunk 64, 8 warps (2m x 4n), warp tile 64x32.
// Padded stride 72 bf16 (144B): 16B/row drift mod 128B => conflict-free ldsm.
#define PLDS 72
#define PJ_SMEM (2 * 128 * PLDS * 2 * 2)   // 73728 B (A + B, 2 bufs)

__device__ __forceinline__ void proj_body(const bf16* __restrict__ A,
                                          const bf16* __restrict__ W,
                                          bf16* __restrict__ out, int Dh,
                                          int bx, int by) {
    extern __shared__ char smem_raw[];
    bf16* sA = (bf16*)smem_raw;                 // [2][128][PLDS]
    bf16* sB = sA + 2 * 128 * PLDS;             // [2][128][PLDS]

    int tid  = threadIdx.x;
    int wid  = tid >> 5;
    int lane = tid & 31;
    int warp_m = wid >> 2;          // 0..1
    int warp_n = wid & 3;           // 0..3
    int rowA0 = by * 128;
    int colB0 = bx * 128;
    int gID = lane >> 2, tig = lane & 3;
    int lsub = lane >> 3, lr = lane & 7;

    float acc[4][4][4];
    #pragma unroll
    for (int mi = 0; mi < 4; mi++)
        #pragma unroll
        for (int nj = 0; nj < 4; nj++)
            #pragma unroll
            for (int q = 0; q < 4; q++) acc[mi][nj][q] = 0.0f;

    // fill one k64 chunk: A 128x64 + B 128x64 = 2048 x 16B ; 8 cpa16/thread
    auto fill = [&](int buf, int k0) {
        #pragma unroll
        for (int p = 0; p < 8; p++) {
            int idx = tid + p * 256;
            int half = idx >> 10;
            int r  = (idx >> 3) & 127;
            int ch = idx & 7;
            const bf16* src = half ? &W[(size_t)(colB0 + r) * DD + k0 + ch * 8]
                                   : &A[(size_t)(rowA0 + r) * DD + k0 + ch * 8];
            bf16* dst = (half ? sB : sA) + (buf * 128 + r) * PLDS + ch * 8;
            cpa16(dst, src);
        }
        cpa_commit();
    };

    fill(0, 0);
    const int NCH = DD / 64;   // 16
    for (int kc = 0; kc < NCH; kc++) {
        int cur = kc & 1;
        cpa_wait0();
        __syncthreads();
        if (kc + 1 < NCH) fill(cur ^ 1, (kc + 1) * 64);

        bf16* pA = sA + cur * 128 * PLDS;
        bf16* pB = sB + cur * 128 * PLDS;
        #pragma unroll
        for (int ks = 0; ks < 2; ks++) {            // two k32 windows
            unsigned aa[4][2][4];
            #pragma unroll
            for (int mi = 0; mi < 4; mi++)
                #pragma unroll
                for (int kh = 0; kh < 2; kh++) {
                    unsigned addr = sm32(&pA[(warp_m * 64 + mi * 16 + (lsub & 1) * 8 + lr) * PLDS
                                             + ks * 32 + kh * 16 + (lsub >> 1) * 8]);
                    ldsm_x4(aa[mi][kh][0], aa[mi][kh][1], aa[mi][kh][2], aa[mi][kh][3], addr);
                }
            #pragma unroll
            for (int nj = 0; nj < 4; nj++) {
                unsigned b0, b1, b2, b3;
                unsigned addr = sm32(&pB[(warp_n * 32 + nj * 8 + lr) * PLDS + ks * 32 + lsub * 8]);
                ldsm_x4(b0, b1, b2, b3, addr);
                #pragma unroll
                for (int mi = 0; mi < 4; mi++) {
                    mma_bf16(acc[mi][nj], aa[mi][0], b0, b1);
                    mma_bf16(acc[mi][nj], aa[mi][1], b2, b3);
                }
            }
        }
    }

    // epilogue: direct bf16x2 stores, coords known per lane
    #pragma unroll
    for (int mi = 0; mi < 4; mi++) {
        int grow0 = rowA0 + warp_m * 64 + mi * 16 + gID;
        #pragma unroll
        for (int half = 0; half < 2; half++) {
            int grow = grow0 + half * 8;
            int b_ = grow >> 11;
            int n_ = grow & 2047;
            #pragma unroll
            for (int nj = 0; nj < 4; nj++) {
                int gcol = colB0 + warp_n * 32 + nj * 8 + 2 * tig;
                int h_ = gcol / Dh;
                int e_ = gcol - h_ * Dh;
                unsigned v = half ? pack_bf2(acc[mi][nj][2], acc[mi][nj][3])
                                  : pack_bf2(acc[mi][nj][0], acc[mi][nj][1]);
                *(unsigned*)(out + (((size_t)b_ * HH + h_) * NN + n_) * Dh + e_) = v;
            }
        }
    }
}

__global__ __launch_bounds__(256)
void proj_qk_kernel(const bf16* __restrict__ A,
                    const bf16* __restrict__ Wq, const bf16* __restrict__ Wk,
                    bf16* __restrict__ Q, bf16* __restrict__ K) {
    if (blockIdx.z == 0) proj_body(A, Wq, Q, DKK, blockIdx.x, blockIdx.y);
    else                 proj_body(A, Wk, K, DKK, blockIdx.x, blockIdx.y);
}

__global__ __launch_bounds__(256)
void proj_v_kernel(const bf16* __restrict__ A, const bf16* __restrict__ Wv,
                   bf16* __restrict__ V) {
    proj_body(A, Wv, V, DVV, blockIdx.x, blockIdx.y);
}

// ---------------- FA2-style fused causal relu-attention (unchanged, R4-passing) ----------------
#define QLDS 136
#define VLDS 264
__global__ __launch_bounds__(256, 1)
void attn_kernel(const bf16* __restrict__ Qg, const bf16* __restrict__ Kg,
                 const bf16* __restrict__ Vg, const float* __restrict__ x,
                 float* __restrict__ out) {
    extern __shared__ char smem_raw[];
    bf16* sQ = (bf16*)smem_raw;
    bf16* sK = sQ + 2 * 64 * QLDS;
    bf16* sV = sK + 2 * 64 * QLDS;

    int tid  = threadIdx.x;
    int lane = tid & 31;
    int wid  = tid >> 5;
    int b_   = blockIdx.z;
    int rowtile = gridDim.y - 1 - blockIdx.y;
    int row0 = rowtile * 64;
    int col0 = blockIdx.x * 256;
    int rg   = (wid >> 1) * 16;
    int ch   = (wid & 1) * 128;
    int ntiles = rowtile + 1;
    int gID = lane >> 2, tig = lane & 3;
    int lsub = lane >> 3, lr = lane & 7;
    const float inv_n = 1.0f / (float)NN;

    float oacc[16][4];
    #pragma unroll
    for (int i = 0; i < 16; i++)
        #pragma unroll
        for (int j = 0; j < 4; j++) oacc[i][j] = 0.0f;

    auto loadQK = [&](bf16* dst, const bf16* src) {
        #pragma unroll
        for (int p = 0; p < 4; p++) {
            int idx = tid + p * 256;
            int r = idx >> 4, c = idx & 15;
            cpa16(&dst[r * QLDS + c * 8], &src[(size_t)r * DKK + c * 8]);
        }
    };
    auto loadV = [&](bf16* dst, const bf16* src) {
        #pragma unroll
        for (int p = 0; p < 8; p++) {
            int idx = tid + p * 256;
            int r = idx >> 5, c = idx & 31;
            cpa16(&dst[r * VLDS + c * 8], &src[(size_t)r * DVV + c * 8]);
        }
    };

    size_t bh0 = (size_t)b_ * HH;
    loadQK(sQ, Qg + bh0 * NN * DKK + (size_t)row0 * DKK);
    loadQK(sK, Kg + bh0 * NN * DKK);
    loadV (sV, Vg + bh0 * NN * DVV + col0);
    cpa_commit();

    unsigned qa[8][4];
    int p = 0;

    for (int h = 0; h < HH; h++) {
        size_t bh = bh0 + h;
        const bf16* Kp = Kg + bh * NN * DKK;
        const bf16* Vp = Vg + bh * NN * DVV + col0;

        for (int mt = 0; mt < ntiles; mt++) {
            cpa_wait0();
            __syncthreads();

            if (mt == 0) {
                bf16* sQh = sQ + (h & 1) * 64 * QLDS;
                int qrow = rg + (lsub & 1) * 8 + lr;
                #pragma unroll
                for (int k = 0; k < 8; k++) {
                    unsigned addr = sm32(&sQh[qrow * QLDS + k * 16 + (lsub >> 1) * 8]);
                    ldsm_x4(qa[k][0], qa[k][1], qa[k][2], qa[k][3], addr);
                }
            }

            if (mt + 1 < ntiles) {
                loadQK(sK + (p ^ 1) * 64 * QLDS, Kp + (size_t)(mt + 1) * 64 * DKK);
                loadV (sV + (p ^ 1) * 64 * VLDS, Vp + (size_t)(mt + 1) * 64 * DVV);
                cpa_commit();
            } else if (h + 1 < HH) {
                loadQK(sQ + ((h + 1) & 1) * 64 * QLDS,
                       Qg + (bh + 1) * NN * DKK + (size_t)row0 * DKK);
                loadQK(sK + (p ^ 1) * 64 * QLDS, Kg + (bh + 1) * NN * DKK);
                loadV (sV + (p ^ 1) * 64 * VLDS, Vg + (bh + 1) * NN * DVV + col0);
                cpa_commit();
            }

            bf16* sKc = sK + p * 64 * QLDS;
            float sc[8][4];
            #pragma unroll
            for (int j = 0; j < 8; j++)
                #pragma unroll
                for (int i = 0; i < 4; i++) sc[j][i] = 0.0f;

            #pragma unroll
            for (int j = 0; j < 8; j++) {
                #pragma unroll
                for (int kp = 0; kp < 4; kp++) {
                    unsigned kb0, kb1, kb2, kb3;
                    unsigned addr = sm32(&sKc[(j * 8 + lr) * QLDS + kp * 32 + lsub * 8]);
                    ldsm_x4(kb0, kb1, kb2, kb3, addr);
                    mma_bf16(sc[j], qa[2 * kp],     kb0, kb1);
                    mma_bf16(sc[j], qa[2 * kp + 1], kb2, kb3);
                }
            }

            int m0 = mt * 64;
            int rowa = row0 + rg + gID;
            int rowb = rowa + 8;
            bool diag = (mt == rowtile);
            unsigned sa[4][4];
            #pragma unroll
            for (int j = 0; j < 8; j++) {
                int cb = m0 + j * 8 + 2 * tig;
                float v0 = fmaxf(sc[j][0], 0.0f) * inv_n;
                float v1 = fmaxf(sc[j][1], 0.0f) * inv_n;
                float v2 = fmaxf(sc[j][2], 0.0f) * inv_n;
                float v3 = fmaxf(sc[j][3], 0.0f) * inv_n;
                if (diag) {
                    if (cb     > rowa) v0 = 0.0f;
                    if (cb + 1 > rowa) v1 = 0.0f;
                    if (cb     > rowb) v2 = 0.0f;
                    if (cb + 1 > rowb) v3 = 0.0f;
                }
                sa[j >> 1][(j & 1) * 2 + 0] = pack_bf2(v0, v1);
                sa[j >> 1][(j & 1) * 2 + 1] = pack_bf2(v2, v3);
            }

            bf16* sVc = sV + p * 64 * VLDS;
            int vrow = (lsub & 1) * 8 + lr;
            int vcol = ch + (lsub >> 1) * 8;
            #pragma unroll
            for (int kt = 0; kt < 4; kt++) {
                #pragma unroll
                for (int np = 0; np < 8; np++) {
                    unsigned v0, v1, v2, v3;
                    unsigned addr = sm32(&sVc[(kt * 16 + vrow) * VLDS + vcol + np * 16]);
                    ldsm_x4_t(v0, v1, v2, v3, addr);
                    mma_bf16(oacc[np * 2],     sa[kt], v0, v1);
                    mma_bf16(oacc[np * 2 + 1], sa[kt], v2, v3);
                }
            }
            p ^= 1;
        }
    }

    #pragma unroll
    for (int nt = 0; nt < 16; nt++) {
        int col = col0 + ch + nt * 8 + 2 * tig;
        size_t g0 = ((size_t)(b_ * NN + row0 + rg + gID)) * DVV + col;
        size_t g1 = g0 + (size_t)8 * DVV;
        float2 xa = *(const float2*)(x + g0);
        float2 xb = *(const float2*)(x + g1);
        float2 ra = {xa.x + oacc[nt][0], xa.y + oacc[nt][1]};
        float2 rb = {xb.x + oacc[nt][2], xb.y + oacc[nt][3]};
        *(float2*)(out + g0) = ra;
        *(float2*)(out + g1) = rb;
    }
}

// ---------------- launch ----------------
extern "C" void kernel_launch(void* const* d_in, const int* in_sizes, int n_in,
                              void* d_out, int out_size) {
    const float* x  = (const float*)d_in[0];
    const float* Wq = (const float*)d_in[1];
    const float* Wk = (const float*)d_in[2];
    const float* Wv = (const float*)d_in[3];
    float* out = (float*)d_out;

    void* p;
    cudaGetSymbolAddress(&p, g_xb); bf16* xb = (bf16*)p;
    cudaGetSymbolAddress(&p, g_wq); bf16* wq = (bf16*)p;
    cudaGetSymbolAddress(&p, g_wk); bf16* wk = (bf16*)p;
    cudaGetSymbolAddress(&p, g_wv); bf16* wv = (bf16*)p;
    cudaGetSymbolAddress(&p, g_Q);  bf16* Q  = (bf16*)p;
    cudaGetSymbolAddress(&p, g_K);  bf16* K  = (bf16*)p;
    cudaGetSymbolAddress(&p, g_V);  bf16* V  = (bf16*)p;

    const int attn_smem = (2 * 64 * QLDS * 2 + 2 * 64 * VLDS) * 2;    // 137216
    static bool attr_done = false;
    if (!attr_done) {
        cudaFuncSetAttribute(proj_qk_kernel,
            cudaFuncAttributeMaxDynamicSharedMemorySize, PJ_SMEM);
        cudaFuncSetAttribute(proj_v_kernel,
            cudaFuncAttributeMaxDynamicSharedMemorySize, PJ_SMEM);
        cudaFuncSetAttribute(attn_kernel,
            cudaFuncAttributeMaxDynamicSharedMemorySize, attn_smem);
        attr_done = true;
    }

    cvt_all_kernel<<<2048, 256>>>((const float4*)x,  (__nv_bfloat162*)xb,
                                  (const float4*)Wq, (__nv_bfloat162*)wq,
                                  (const float4*)Wk, (__nv_bfloat162*)wk,
                                  (const float4*)Wv, (__nv_bfloat162*)wv);

    proj_qk_kernel<<<dim3(HH * DKK / 128, BB * NN / 128, 2), 256, PJ_SMEM>>>(xb, wq, wk, Q, K);
    proj_v_kernel <<<dim3(HH * DVV / 128, BB * NN / 128),    256, PJ_SMEM>>>(xb, wv, V);

    attn_kernel<<<dim3(DVV / 256, NN / 64, BB), 256, attn_smem>>>(Q, K, V, x, out);
}

// round 10
// speedup vs baseline: 4.6241x; 1.0075x over previous
#include <cuda_runtime.h>
#include <cuda_bf16.h>
#include <cstdint>
#include <cmath>

using bf16 = __nv_bfloat16;

#define BB  2
#define NN  2048
#define DD  1024
#define HH  8
#define DKK 128
#define DVV 1024

// ---------------- static scratch (no allocations allowed) ----------------
__device__ bf16 g_xb[BB * NN * DD];
__device__ bf16 g_wq[HH * DKK * DD];
__device__ bf16 g_wk[HH * DKK * DD];
__device__ bf16 g_wv[HH * DVV * DD];
__device__ bf16 g_Q [BB * HH * NN * DKK];
__device__ bf16 g_K [BB * HH * NN * DKK];
__device__ bf16 g_V [BB * HH * NN * DVV];
__device__ bf16 g_S [(size_t)BB * HH * NN * NN];   // 134 MB masked-relu scores

// ---------------- asm helpers ----------------
__device__ __forceinline__ void cpa16(void* dst_smem, const void* src_gmem) {
    unsigned d = (unsigned)__cvta_generic_to_shared(dst_smem);
    asm volatile("cp.async.cg.shared.global [%0], [%1], 16;\n" :: "r"(d), "l"(src_gmem));
}
__device__ __forceinline__ void cpa_commit() {
    asm volatile("cp.async.commit_group;\n" ::: "memory");
}
__device__ __forceinline__ void cpa_wait0() {
    asm volatile("cp.async.wait_group 0;\n" ::: "memory");
}
__device__ __forceinline__ unsigned sm32(const void* p) {
    return (unsigned)__cvta_generic_to_shared(p);
}
__device__ __forceinline__ void ldsm_x4(unsigned& r0, unsigned& r1, unsigned& r2,
                                        unsigned& r3, unsigned addr) {
    asm volatile("ldmatrix.sync.aligned.m8n8.x4.shared.b16 {%0,%1,%2,%3}, [%4];\n"
                 : "=r"(r0), "=r"(r1), "=r"(r2), "=r"(r3) : "r"(addr));
}
__device__ __forceinline__ void ldsm_x4_t(unsigned& r0, unsigned& r1, unsigned& r2,
                                          unsigned& r3, unsigned addr) {
    asm volatile("ldmatrix.sync.aligned.m8n8.x4.trans.shared.b16 {%0,%1,%2,%3}, [%4];\n"
                 : "=r"(r0), "=r"(r1), "=r"(r2), "=r"(r3) : "r"(addr));
}
__device__ __forceinline__ void mma_bf16(float c[4], const unsigned a[4],
                                         unsigned b0, unsigned b1) {
    asm volatile("mma.sync.aligned.m16n8k16.row.col.f32.bf16.bf16.f32 "
                 "{%0,%1,%2,%3}, {%4,%5,%6,%7}, {%8,%9}, {%0,%1,%2,%3};\n"
                 : "+f"(c[0]), "+f"(c[1]), "+f"(c[2]), "+f"(c[3])
                 : "r"(a[0]), "r"(a[1]), "r"(a[2]), "r"(a[3]), "r"(b0), "r"(b1));
}
__device__ __forceinline__ unsigned pack_bf2(float lo, float hi) {
    unsigned r;
    asm("cvt.rn.bf16x2.f32 %0, %1, %2;\n" : "=r"(r) : "f"(hi), "f"(lo));
    return r;
}

// ---------------- fused fp32 -> bf16 conversion ----------------
__global__ void cvt_all_kernel(const float4* __restrict__ x,  __nv_bfloat162* __restrict__ xb,
                               const float4* __restrict__ wq, __nv_bfloat162* __restrict__ wqb,
                               const float4* __restrict__ wk, __nv_bfloat162* __restrict__ wkb,
                               const float4* __restrict__ wv, __nv_bfloat162* __restrict__ wvb) {
    const int n0 = BB * NN * DD / 4;
    const int n1 = HH * DKK * DD / 4;
    const int n2 = HH * DVV * DD / 4;
    const int total = n0 + 2 * n1 + n2;
    int i = blockIdx.x * blockDim.x + threadIdx.x;
    int stride = gridDim.x * blockDim.x;
    for (; i < total; i += stride) {
        const float4* src;
        __nv_bfloat162* dst;
        int j = i;
        if (j < n0) { src = x; dst = xb; }
        else if ((j -= n0) < n1) { src = wq; dst = wqb; }
        else if ((j -= n1) < n1) { src = wk; dst = wkb; }
        else { j -= n1; src = wv; dst = wvb; }
        float4 v = src[j];
        dst[2 * j]     = __floats2bfloat162_rn(v.x, v.y);
        dst[2 * j + 1] = __floats2bfloat162_rn(v.z, v.w);
    }
}

// ---------------- projection GEMM (unchanged from R6-passing) ----------------
#define PLDS 72
#define PJ_SMEM (2 * 128 * PLDS * 2 * 2)

__device__ __forceinline__ void proj_body(const bf16* __restrict__ A,
                                          const bf16* __restrict__ W,
                                          bf16* __restrict__ out, int Dh,
                                          int bx, int by) {
    extern __shared__ char smem_raw[];
    bf16* sA = (bf16*)smem_raw;
    bf16* sB = sA + 2 * 128 * PLDS;

    int tid  = threadIdx.x;
    int wid  = tid >> 5;
    int lane = tid & 31;
    int warp_m = wid >> 2;
    int warp_n = wid & 3;
    int rowA0 = by * 128;
    int colB0 = bx * 128;
    int gID = lane >> 2, tig = lane & 3;
    int lsub = lane >> 3, lr = lane & 7;

    float acc[4][4][4];
    #pragma unroll
    for (int mi = 0; mi < 4; mi++)
        #pragma unroll
        for (int nj = 0; nj < 4; nj++)
            #pragma unroll
            for (int q = 0; q < 4; q++) acc[mi][nj][q] = 0.0f;

    auto fill = [&](int buf, int k0) {
        #pragma unroll
        for (int p = 0; p < 8; p++) {
            int idx = tid + p * 256;
            int half = idx >> 10;
            int r  = (idx >> 3) & 127;
            int ch = idx & 7;
            const bf16* src = half ? &W[(size_t)(colB0 + r) * DD + k0 + ch * 8]
                                   : &A[(size_t)(rowA0 + r) * DD + k0 + ch * 8];
            bf16* dst = (half ? sB : sA) + (buf * 128 + r) * PLDS + ch * 8;
            cpa16(dst, src);
        }
        cpa_commit();
    };

    fill(0, 0);
    const int NCH = DD / 64;
    for (int kc = 0; kc < NCH; kc++) {
        int cur = kc & 1;
        cpa_wait0();
        __syncthreads();
        if (kc + 1 < NCH) fill(cur ^ 1, (kc + 1) * 64);

        bf16* pA = sA + cur * 128 * PLDS;
        bf16* pB = sB + cur * 128 * PLDS;
        #pragma unroll
        for (int ks = 0; ks < 2; ks++) {
            unsigned aa[4][2][4];
            #pragma unroll
            for (int mi = 0; mi < 4; mi++)
                #pragma unroll
                for (int kh = 0; kh < 2; kh++) {
                    unsigned addr = sm32(&pA[(warp_m * 64 + mi * 16 + (lsub & 1) * 8 + lr) * PLDS
                                             + ks * 32 + kh * 16 + (lsub >> 1) * 8]);
                    ldsm_x4(aa[mi][kh][0], aa[mi][kh][1], aa[mi][kh][2], aa[mi][kh][3], addr);
                }
            #pragma unroll
            for (int nj = 0; nj < 4; nj++) {
                unsigned b0, b1, b2, b3;
                unsigned addr = sm32(&pB[(warp_n * 32 + nj * 8 + lr) * PLDS + ks * 32 + lsub * 8]);
                ldsm_x4(b0, b1, b2, b3, addr);
                #pragma unroll
                for (int mi = 0; mi < 4; mi++) {
                    mma_bf16(acc[mi][nj], aa[mi][0], b0, b1);
                    mma_bf16(acc[mi][nj], aa[mi][1], b2, b3);
                }
            }
        }
    }

    #pragma unroll
    for (int mi = 0; mi < 4; mi++) {
        int grow0 = rowA0 + warp_m * 64 + mi * 16 + gID;
        #pragma unroll
        for (int half = 0; half < 2; half++) {
            int grow = grow0 + half * 8;
            int b_ = grow >> 11;
            int n_ = grow & 2047;
            #pragma unroll
            for (int nj = 0; nj < 4; nj++) {
                int gcol = colB0 + warp_n * 32 + nj * 8 + 2 * tig;
                int h_ = gcol / Dh;
                int e_ = gcol - h_ * Dh;
                unsigned v = half ? pack_bf2(acc[mi][nj][2], acc[mi][nj][3])
                                  : pack_bf2(acc[mi][nj][0], acc[mi][nj][1]);
                *(unsigned*)(out + (((size_t)b_ * HH + h_) * NN + n_) * Dh + e_) = v;
            }
        }
    }
}

__global__ __launch_bounds__(256)
void proj_qk_kernel(const bf16* __restrict__ A,
                    const bf16* __restrict__ Wq, const bf16* __restrict__ Wk,
                    bf16* __restrict__ Q, bf16* __restrict__ K) {
    if (blockIdx.z == 0) proj_body(A, Wq, Q, DKK, blockIdx.x, blockIdx.y);
    else                 proj_body(A, Wk, K, DKK, blockIdx.x, blockIdx.y);
}

__global__ __launch_bounds__(256)
void proj_v_kernel(const bf16* __restrict__ A, const bf16* __restrict__ Wv,
                   bf16* __restrict__ V) {
    proj_body(A, Wv, V, DVV, blockIdx.x, blockIdx.y);
}

// ---------------- S kernel: S = relu(mask(Q K^T))/N -> bf16 gmem ----------------
// One 128x128 tile per CTA over the lower triangle (136 tiles) x (H) x (B).
#define KLDS 136
#define S_SMEM (2 * 128 * KLDS * 2)   // Q + K tiles, 69632 B

__global__ __launch_bounds__(256)
void s_kernel(const bf16* __restrict__ Qg, const bf16* __restrict__ Kg,
              bf16* __restrict__ Sg) {
    extern __shared__ char smem_raw[];
    bf16* sQ = (bf16*)smem_raw;           // [128][KLDS]
    bf16* sK = sQ + 128 * KLDS;           // [128][KLDS]

    int tid  = threadIdx.x;
    int lane = tid & 31;
    int wid  = tid >> 5;
    int h  = blockIdx.y;
    int b_ = blockIdx.z;

    // triangle decode: t -> (rt, ct), ct <= rt
    int t = blockIdx.x;
    int rt = (int)((sqrtf(8.0f * (float)t + 1.0f) - 1.0f) * 0.5f);
    while ((rt + 1) * (rt + 2) / 2 <= t) rt++;
    while (rt * (rt + 1) / 2 > t) rt--;
    int ct = t - rt * (rt + 1) / 2;
    int n0 = rt * 128, m0 = ct * 128;

    const bf16* Qp = Qg + ((size_t)(b_ * HH + h) * NN + n0) * DKK;
    const bf16* Kp = Kg + ((size_t)(b_ * HH + h) * NN + m0) * DKK;

    // load Q and K tiles (128x128 bf16 each = 2048 x 16B chunks each; 8/thread)
    #pragma unroll
    for (int p = 0; p < 8; p++) {
        int idx = tid + p * 256;
        int r = idx >> 4, c = idx & 15;
        cpa16(&sQ[r * KLDS + c * 8], &Qp[(size_t)r * DKK + c * 8]);
        cpa16(&sK[r * KLDS + c * 8], &Kp[(size_t)r * DKK + c * 8]);
    }
    cpa_commit();
    cpa_wait0();
    __syncthreads();

    int rg = wid * 16;
    int gID = lane >> 2, tig = lane & 3;
    int lsub = lane >> 3, lr = lane & 7;

    unsigned qa[8][4];
    int qrow = rg + (lsub & 1) * 8 + lr;
    #pragma unroll
    for (int k = 0; k < 8; k++) {
        unsigned addr = sm32(&sQ[qrow * KLDS + k * 16 + (lsub >> 1) * 8]);
        ldsm_x4(qa[k][0], qa[k][1], qa[k][2], qa[k][3], addr);
    }

    float sc[16][4];
    #pragma unroll
    for (int j = 0; j < 16; j++)
        #pragma unroll
        for (int i = 0; i < 4; i++) sc[j][i] = 0.0f;

    #pragma unroll
    for (int j = 0; j < 16; j++) {
        #pragma unroll
        for (int kp = 0; kp < 4; kp++) {
            unsigned kb0, kb1, kb2, kb3;
            unsigned addr = sm32(&sK[(j * 8 + lr) * KLDS + kp * 32 + lsub * 8]);
            ldsm_x4(kb0, kb1, kb2, kb3, addr);
            mma_bf16(sc[j], qa[2 * kp],     kb0, kb1);
            mma_bf16(sc[j], qa[2 * kp + 1], kb2, kb3);
        }
    }

    // relu + causal mask + /N, pack, store
    const float inv_n = 1.0f / (float)NN;
    bool diag = (rt == ct);
    int rowa = n0 + rg + gID;
    int rowb = rowa + 8;
    bf16* Sp = Sg + (size_t)(b_ * HH + h) * NN * NN;
    #pragma unroll
    for (int j = 0; j < 16; j++) {
        int m = m0 + j * 8 + 2 * tig;
        float v0 = fmaxf(sc[j][0], 0.0f) * inv_n;
        float v1 = fmaxf(sc[j][1], 0.0f) * inv_n;
        float v2 = fmaxf(sc[j][2], 0.0f) * inv_n;
        float v3 = fmaxf(sc[j][3], 0.0f) * inv_n;
        if (diag) {
            if (m     > rowa) v0 = 0.0f;
            if (m + 1 > rowa) v1 = 0.0f;
            if (m     > rowb) v2 = 0.0f;
            if (m + 1 > rowb) v3 = 0.0f;
        }
        *(unsigned*)&Sp[(size_t)rowa * NN + m] = pack_bf2(v0, v1);
        *(unsigned*)&Sp[(size_t)rowb * NN + m] = pack_bf2(v2, v3);
    }
}

// ---------------- PV kernel: out = x + sum_h S @ V ----------------
#define SLDS 72
#define VLDS 264
#define PV_SMEM (2 * 64 * SLDS * 2 + 2 * 64 * VLDS * 2)   // 86016 B

__global__ __launch_bounds__(256, 2)
void pv_kernel(const bf16* __restrict__ Sg, const bf16* __restrict__ Vg,
               const float* __restrict__ x, float* __restrict__ out) {
    extern __shared__ char smem_raw[];
    bf16* sS = (bf16*)smem_raw;            // [2][64][SLDS]
    bf16* sV = sS + 2 * 64 * SLDS;         // [2][64][VLDS]

    int tid  = threadIdx.x;
    int lane = tid & 31;
    int wid  = tid >> 5;
    int b_   = blockIdx.z;
    int rowtile = gridDim.y - 1 - blockIdx.y;   // heavy first
    int row0 = rowtile * 64;
    int col0 = blockIdx.x * 256;
    int rg   = (wid >> 1) * 16;
    int ch   = (wid & 1) * 128;
    int ntiles = rowtile + 1;
    int gID = lane >> 2, tig = lane & 3;
    int lsub = lane >> 3, lr = lane & 7;

    const bf16* Sb = Sg + (size_t)b_ * HH * NN * NN;
    const bf16* Vb = Vg + (size_t)b_ * HH * NN * DVV;

    float oacc[16][4];
    #pragma unroll
    for (int i = 0; i < 16; i++)
        #pragma unroll
        for (int j = 0; j < 4; j++) oacc[i][j] = 0.0f;

    auto loadS = [&](bf16* dst, int hh, int mt) {
        const bf16* src = Sb + ((size_t)hh * NN + row0) * NN + mt * 64;
        #pragma unroll
        for (int p = 0; p < 2; p++) {
            int idx = tid + p * 256;
            int r = idx >> 3, c = idx & 7;
            cpa16(&dst[r * SLDS + c * 8], &src[(size_t)r * NN + c * 8]);
        }
    };
    auto loadV = [&](bf16* dst, int hh, int mt) {
        const bf16* src = Vb + ((size_t)hh * NN + mt * 64) * DVV + col0;
        #pragma unroll
        for (int p = 0; p < 8; p++) {
            int idx = tid + p * 256;
            int r = idx >> 5, c = idx & 31;
            cpa16(&dst[r * VLDS + c * 8], &src[(size_t)r * DVV + c * 8]);
        }
    };

    loadS(sS, 0, 0);
    loadV(sV, 0, 0);
    cpa_commit();

    int p = 0;
    for (int h = 0; h < HH; h++) {
        for (int mt = 0; mt < ntiles; mt++) {
            cpa_wait0();
            __syncthreads();

            int nh = h, nmt = mt + 1;
            if (nmt == ntiles) { nh = h + 1; nmt = 0; }
            if (nh < HH) {
                loadS(sS + (p ^ 1) * 64 * SLDS, nh, nmt);
                loadV(sV + (p ^ 1) * 64 * VLDS, nh, nmt);
                cpa_commit();
            }

            // A-frags from sS (16 rows x 64 k)
            bf16* sSc = sS + p * 64 * SLDS;
            int arow = rg + (lsub & 1) * 8 + lr;
            unsigned sa[4][4];
            #pragma unroll
            for (int kt = 0; kt < 4; kt++) {
                unsigned addr = sm32(&sSc[arow * SLDS + kt * 16 + (lsub >> 1) * 8]);
                ldsm_x4(sa[kt][0], sa[kt][1], sa[kt][2], sa[kt][3], addr);
            }

            bf16* sVc = sV + p * 64 * VLDS;
            int vrow = (lsub & 1) * 8 + lr;
            int vcol = ch + (lsub >> 1) * 8;
            #pragma unroll
            for (int kt = 0; kt < 4; kt++) {
                #pragma unroll
                for (int np = 0; np < 8; np++) {
                    unsigned v0, v1, v2, v3;
                    unsigned addr = sm32(&sVc[(kt * 16 + vrow) * VLDS + vcol + np * 16]);
                    ldsm_x4_t(v0, v1, v2, v3, addr);
                    mma_bf16(oacc[np * 2],     sa[kt], v0, v1);
                    mma_bf16(oacc[np * 2 + 1], sa[kt], v2, v3);
                }
            }
            p ^= 1;
        }
    }

    #pragma unroll
    for (int nt = 0; nt < 16; nt++) {
        int col = col0 + ch + nt * 8 + 2 * tig;
        size_t g0 = ((size_t)(b_ * NN + row0 + rg + gID)) * DVV + col;
        size_t g1 = g0 + (size_t)8 * DVV;
        float2 xa = *(const float2*)(x + g0);
        float2 xb = *(const float2*)(x + g1);
        float2 ra = {xa.x + oacc[nt][0], xa.y + oacc[nt][1]};
        float2 rb = {xb.x + oacc[nt][2], xb.y + oacc[nt][3]};
        *(float2*)(out + g0) = ra;
        *(float2*)(out + g1) = rb;
    }
}

// ---------------- launch ----------------
extern "C" void kernel_launch(void* const* d_in, const int* in_sizes, int n_in,
                              void* d_out, int out_size) {
    const float* x  = (const float*)d_in[0];
    const float* Wq = (const float*)d_in[1];
    const float* Wk = (const float*)d_in[2];
    const float* Wv = (const float*)d_in[3];
    float* out = (float*)d_out;

    void* p;
    cudaGetSymbolAddress(&p, g_xb); bf16* xb = (bf16*)p;
    cudaGetSymbolAddress(&p, g_wq); bf16* wq = (bf16*)p;
    cudaGetSymbolAddress(&p, g_wk); bf16* wk = (bf16*)p;
    cudaGetSymbolAddress(&p, g_wv); bf16* wv = (bf16*)p;
    cudaGetSymbolAddress(&p, g_Q);  bf16* Q  = (bf16*)p;
    cudaGetSymbolAddress(&p, g_K);  bf16* K  = (bf16*)p;
    cudaGetSymbolAddress(&p, g_V);  bf16* V  = (bf16*)p;
    cudaGetSymbolAddress(&p, g_S);  bf16* S  = (bf16*)p;

    static bool attr_done = false;
    if (!attr_done) {
        cudaFuncSetAttribute(proj_qk_kernel,
            cudaFuncAttributeMaxDynamicSharedMemorySize, PJ_SMEM);
        cudaFuncSetAttribute(proj_v_kernel,
            cudaFuncAttributeMaxDynamicSharedMemorySize, PJ_SMEM);
        cudaFuncSetAttribute(s_kernel,
            cudaFuncAttributeMaxDynamicSharedMemorySize, S_SMEM);
        cudaFuncSetAttribute(pv_kernel,
            cudaFuncAttributeMaxDynamicSharedMemorySize, PV_SMEM);
        attr_done = true;
    }

    cvt_all_kernel<<<2048, 256>>>((const float4*)x,  (__nv_bfloat162*)xb,
                                  (const float4*)Wq, (__nv_bfloat162*)wq,
                                  (const float4*)Wk, (__nv_bfloat162*)wk,
                                  (const float4*)Wv, (__nv_bfloat162*)wv);

    proj_qk_kernel<<<dim3(HH * DKK / 128, BB * NN / 128, 2), 256, PJ_SMEM>>>(xb, wq, wk, Q, K);
    proj_v_kernel <<<dim3(HH * DVV / 128, BB * NN / 128),    256, PJ_SMEM>>>(xb, wv, V);

    // S = relu(mask(Q K^T))/N over the causal lower triangle (136 tile pairs)
    s_kernel<<<dim3(136, HH, BB), 256, S_SMEM>>>(Q, K, S);

    // out = x + sum_h S @ V
    pv_kernel<<<dim3(DVV / 256, NN / 64, BB), 256, PV_SMEM>>>(S, V, x, out);
}

// round 11
// speedup vs baseline: 4.8526x; 1.0494x over previous
#include <cuda_runtime.h>
#include <cuda_bf16.h>
#include <cstdint>
#include <cmath>

using bf16 = __nv_bfloat16;

#define BB  2
#define NN  2048
#define DD  1024
#define HH  8
#define DKK 128
#define DVV 1024

// ---------------- static scratch (no allocations allowed) ----------------
__device__ bf16 g_xb[BB * NN * DD];
__device__ bf16 g_wq[HH * DKK * DD];
__device__ bf16 g_wk[HH * DKK * DD];
__device__ bf16 g_wv[HH * DVV * DD];
__device__ bf16 g_Q [BB * HH * NN * DKK];
__device__ bf16 g_K [BB * HH * NN * DKK];
__device__ bf16 g_V [BB * HH * NN * DVV];
__device__ bf16 g_S [(size_t)BB * HH * NN * NN];   // masked-relu scores

// ---------------- asm helpers ----------------
__device__ __forceinline__ void cpa16(void* dst_smem, const void* src_gmem) {
    unsigned d = (unsigned)__cvta_generic_to_shared(dst_smem);
    asm volatile("cp.async.cg.shared.global [%0], [%1], 16;\n" :: "r"(d), "l"(src_gmem));
}
__device__ __forceinline__ void cpa_commit() {
    asm volatile("cp.async.commit_group;\n" ::: "memory");
}
__device__ __forceinline__ void cpa_wait0() {
    asm volatile("cp.async.wait_group 0;\n" ::: "memory");
}
__device__ __forceinline__ unsigned sm32(const void* p) {
    return (unsigned)__cvta_generic_to_shared(p);
}
__device__ __forceinline__ void ldsm_x4(unsigned& r0, unsigned& r1, unsigned& r2,
                                        unsigned& r3, unsigned addr) {
    asm volatile("ldmatrix.sync.aligned.m8n8.x4.shared.b16 {%0,%1,%2,%3}, [%4];\n"
                 : "=r"(r0), "=r"(r1), "=r"(r2), "=r"(r3) : "r"(addr));
}
__device__ __forceinline__ void ldsm_x4_t(unsigned& r0, unsigned& r1, unsigned& r2,
                                          unsigned& r3, unsigned addr) {
    asm volatile("ldmatrix.sync.aligned.m8n8.x4.trans.shared.b16 {%0,%1,%2,%3}, [%4];\n"
                 : "=r"(r0), "=r"(r1), "=r"(r2), "=r"(r3) : "r"(addr));
}
__device__ __forceinline__ void mma_bf16(float c[4], const unsigned a[4],
                                         unsigned b0, unsigned b1) {
    asm volatile("mma.sync.aligned.m16n8k16.row.col.f32.bf16.bf16.f32 "
                 "{%0,%1,%2,%3}, {%4,%5,%6,%7}, {%8,%9}, {%0,%1,%2,%3};\n"
                 : "+f"(c[0]), "+f"(c[1]), "+f"(c[2]), "+f"(c[3])
                 : "r"(a[0]), "r"(a[1]), "r"(a[2]), "r"(a[3]), "r"(b0), "r"(b1));
}
__device__ __forceinline__ void mma_bf16_k16(float c[4], unsigned a0, unsigned a1,
                                             unsigned a2, unsigned a3,
                                             unsigned b0, unsigned b1) {
    asm volatile("mma.sync.aligned.m16n8k16.row.col.f32.bf16.bf16.f32 "
                 "{%0,%1,%2,%3}, {%4,%5,%6,%7}, {%8,%9}, {%0,%1,%2,%3};\n"
                 : "+f"(c[0]), "+f"(c[1]), "+f"(c[2]), "+f"(c[3])
                 : "r"(a0), "r"(a1), "r"(a2), "r"(a3), "r"(b0), "r"(b1));
}
__device__ __forceinline__ unsigned pack_bf2(float lo, float hi) {
    unsigned r;
    asm("cvt.rn.bf16x2.f32 %0, %1, %2;\n" : "=r"(r) : "f"(hi), "f"(lo));
    return r;
}

// ---------------- fused fp32 -> bf16 conversion ----------------
__global__ void cvt_all_kernel(const float4* __restrict__ x,  __nv_bfloat162* __restrict__ xb,
                               const float4* __restrict__ wq, __nv_bfloat162* __restrict__ wqb,
                               const float4* __restrict__ wk, __nv_bfloat162* __restrict__ wkb,
                               const float4* __restrict__ wv, __nv_bfloat162* __restrict__ wvb) {
    const int n0 = BB * NN * DD / 4;
    const int n1 = HH * DKK * DD / 4;
    const int n2 = HH * DVV * DD / 4;
    const int total = n0 + 2 * n1 + n2;
    int i = blockIdx.x * blockDim.x + threadIdx.x;
    int stride = gridDim.x * blockDim.x;
    for (; i < total; i += stride) {
        const float4* src;
        __nv_bfloat162* dst;
        int j = i;
        if (j < n0) { src = x; dst = xb; }
        else if ((j -= n0) < n1) { src = wq; dst = wqb; }
        else if ((j -= n1) < n1) { src = wk; dst = wkb; }
        else { j -= n1; src = wv; dst = wvb; }
        float4 v = src[j];
        dst[2 * j]     = __floats2bfloat162_rn(v.x, v.y);
        dst[2 * j + 1] = __floats2bfloat162_rn(v.z, v.w);
    }
}

// ---------------- projection GEMM (unchanged, passing) ----------------
#define PLDS 72
#define PJ_SMEM (2 * 128 * PLDS * 2 * 2)

__device__ __forceinline__ void proj_body(const bf16* __restrict__ A,
                                          const bf16* __restrict__ W,
                                          bf16* __restrict__ out, int Dh,
                                          int bx, int by) {
    extern __shared__ char smem_raw[];
    bf16* sA = (bf16*)smem_raw;
    bf16* sB = sA + 2 * 128 * PLDS;

    int tid  = threadIdx.x;
    int wid  = tid >> 5;
    int lane = tid & 31;
    int warp_m = wid >> 2;
    int warp_n = wid & 3;
    int rowA0 = by * 128;
    int colB0 = bx * 128;
    int gID = lane >> 2, tig = lane & 3;
    int lsub = lane >> 3, lr = lane & 7;

    float acc[4][4][4];
    #pragma unroll
    for (int mi = 0; mi < 4; mi++)
        #pragma unroll
        for (int nj = 0; nj < 4; nj++)
            #pragma unroll
            for (int q = 0; q < 4; q++) acc[mi][nj][q] = 0.0f;

    auto fill = [&](int buf, int k0) {
        #pragma unroll
        for (int p = 0; p < 8; p++) {
            int idx = tid + p * 256;
            int half = idx >> 10;
            int r  = (idx >> 3) & 127;
            int ch = idx & 7;
            const bf16* src = half ? &W[(size_t)(colB0 + r) * DD + k0 + ch * 8]
                                   : &A[(size_t)(rowA0 + r) * DD + k0 + ch * 8];
            bf16* dst = (half ? sB : sA) + (buf * 128 + r) * PLDS + ch * 8;
            cpa16(dst, src);
        }
        cpa_commit();
    };

    fill(0, 0);
    const int NCH = DD / 64;
    for (int kc = 0; kc < NCH; kc++) {
        int cur = kc & 1;
        cpa_wait0();
        __syncthreads();
        if (kc + 1 < NCH) fill(cur ^ 1, (kc + 1) * 64);

        bf16* pA = sA + cur * 128 * PLDS;
        bf16* pB = sB + cur * 128 * PLDS;
        #pragma unroll
        for (int ks = 0; ks < 2; ks++) {
            unsigned aa[4][2][4];
            #pragma unroll
            for (int mi = 0; mi < 4; mi++)
                #pragma unroll
                for (int kh = 0; kh < 2; kh++) {
                    unsigned addr = sm32(&pA[(warp_m * 64 + mi * 16 + (lsub & 1) * 8 + lr) * PLDS
                                             + ks * 32 + kh * 16 + (lsub >> 1) * 8]);
                    ldsm_x4(aa[mi][kh][0], aa[mi][kh][1], aa[mi][kh][2], aa[mi][kh][3], addr);
                }
            #pragma unroll
            for (int nj = 0; nj < 4; nj++) {
                unsigned b0, b1, b2, b3;
                unsigned addr = sm32(&pB[(warp_n * 32 + nj * 8 + lr) * PLDS + ks * 32 + lsub * 8]);
                ldsm_x4(b0, b1, b2, b3, addr);
                #pragma unroll
                for (int mi = 0; mi < 4; mi++) {
                    mma_bf16(acc[mi][nj], aa[mi][0], b0, b1);
                    mma_bf16(acc[mi][nj], aa[mi][1], b2, b3);
                }
            }
        }
    }

    #pragma unroll
    for (int mi = 0; mi < 4; mi++) {
        int grow0 = rowA0 + warp_m * 64 + mi * 16 + gID;
        #pragma unroll
        for (int half = 0; half < 2; half++) {
            int grow = grow0 + half * 8;
            int b_ = grow >> 11;
            int n_ = grow & 2047;
            #pragma unroll
            for (int nj = 0; nj < 4; nj++) {
                int gcol = colB0 + warp_n * 32 + nj * 8 + 2 * tig;
                int h_ = gcol / Dh;
                int e_ = gcol - h_ * Dh;
                unsigned v = half ? pack_bf2(acc[mi][nj][2], acc[mi][nj][3])
                                  : pack_bf2(acc[mi][nj][0], acc[mi][nj][1]);
                *(unsigned*)(out + (((size_t)b_ * HH + h_) * NN + n_) * Dh + e_) = v;
            }
        }
    }
}

__global__ __launch_bounds__(256)
void proj_qk_kernel(const bf16* __restrict__ A,
                    const bf16* __restrict__ Wq, const bf16* __restrict__ Wk,
                    bf16* __restrict__ Q, bf16* __restrict__ K) {
    if (blockIdx.z == 0) proj_body(A, Wq, Q, DKK, blockIdx.x, blockIdx.y);
    else                 proj_body(A, Wk, K, DKK, blockIdx.x, blockIdx.y);
}

__global__ __launch_bounds__(256)
void proj_v_kernel(const bf16* __restrict__ A, const bf16* __restrict__ Wv,
                   bf16* __restrict__ V) {
    proj_body(A, Wv, V, DVV, blockIdx.x, blockIdx.y);
}

// ---------------- S kernel (unchanged, passing; 55.7us) ----------------
#define KLDS 136
#define S_SMEM (2 * 128 * KLDS * 2)

__global__ __launch_bounds__(256)
void s_kernel(const bf16* __restrict__ Qg, const bf16* __restrict__ Kg,
              bf16* __restrict__ Sg) {
    extern __shared__ char smem_raw[];
    bf16* sQ = (bf16*)smem_raw;
    bf16* sK = sQ + 128 * KLDS;

    int tid  = threadIdx.x;
    int lane = tid & 31;
    int wid  = tid >> 5;
    int h  = blockIdx.y;
    int b_ = blockIdx.z;

    int t = blockIdx.x;
    int rt = (int)((sqrtf(8.0f * (float)t + 1.0f) - 1.0f) * 0.5f);
    while ((rt + 1) * (rt + 2) / 2 <= t) rt++;
    while (rt * (rt + 1) / 2 > t) rt--;
    int ct = t - rt * (rt + 1) / 2;
    int n0 = rt * 128, m0 = ct * 128;

    const bf16* Qp = Qg + ((size_t)(b_ * HH + h) * NN + n0) * DKK;
    const bf16* Kp = Kg + ((size_t)(b_ * HH + h) * NN + m0) * DKK;

    #pragma unroll
    for (int p = 0; p < 8; p++) {
        int idx = tid + p * 256;
        int r = idx >> 4, c = idx & 15;
        cpa16(&sQ[r * KLDS + c * 8], &Qp[(size_t)r * DKK + c * 8]);
        cpa16(&sK[r * KLDS + c * 8], &Kp[(size_t)r * DKK + c * 8]);
    }
    cpa_commit();
    cpa_wait0();
    __syncthreads();

    int rg = wid * 16;
    int gID = lane >> 2, tig = lane & 3;
    int lsub = lane >> 3, lr = lane & 7;

    unsigned qa[8][4];
    int qrow = rg + (lsub & 1) * 8 + lr;
    #pragma unroll
    for (int k = 0; k < 8; k++) {
        unsigned addr = sm32(&sQ[qrow * KLDS + k * 16 + (lsub >> 1) * 8]);
        ldsm_x4(qa[k][0], qa[k][1], qa[k][2], qa[k][3], addr);
    }

    float sc[16][4];
    #pragma unroll
    for (int j = 0; j < 16; j++)
        #pragma unroll
        for (int i = 0; i < 4; i++) sc[j][i] = 0.0f;

    #pragma unroll
    for (int j = 0; j < 16; j++) {
        #pragma unroll
        for (int kp = 0; kp < 4; kp++) {
            unsigned kb0, kb1, kb2, kb3;
            unsigned addr = sm32(&sK[(j * 8 + lr) * KLDS + kp * 32 + lsub * 8]);
            ldsm_x4(kb0, kb1, kb2, kb3, addr);
            mma_bf16(sc[j], qa[2 * kp],     kb0, kb1);
            mma_bf16(sc[j], qa[2 * kp + 1], kb2, kb3);
        }
    }

    const float inv_n = 1.0f / (float)NN;
    bool diag = (rt == ct);
    int rowa = n0 + rg + gID;
    int rowb = rowa + 8;
    bf16* Sp = Sg + (size_t)(b_ * HH + h) * NN * NN;
    #pragma unroll
    for (int j = 0; j < 16; j++) {
        int m = m0 + j * 8 + 2 * tig;
        float v0 = fmaxf(sc[j][0], 0.0f) * inv_n;
        float v1 = fmaxf(sc[j][1], 0.0f) * inv_n;
        float v2 = fmaxf(sc[j][2], 0.0f) * inv_n;
        float v3 = fmaxf(sc[j][3], 0.0f) * inv_n;
        if (diag) {
            if (m     > rowa) v0 = 0.0f;
            if (m + 1 > rowa) v1 = 0.0f;
            if (m     > rowb) v2 = 0.0f;
            if (m + 1 > rowb) v3 = 0.0f;
        }
        *(unsigned*)&Sp[(size_t)rowa * NN + m] = pack_bf2(v0, v1);
        *(unsigned*)&Sp[(size_t)rowb * NN + m] = pack_bf2(v2, v3);
    }
}

// ---------------- PV kernel: out = x + sum_h S @ V (retiled) ----------------
// CTA 64 rows x 256 cols; 8 warps as 2m x 4n, warp tile 32x64.
// Per m-tile per warp: 8 A-ldsm + 16 V-ldsm, 64 mma (was 36 ldsm).
// k16-split inner loop keeps live temps at 12 regs -> fits 128-reg cap (occ 2).
#define SLDS 72
#define VLDS 264
#define PV_SMEM (2 * 64 * SLDS * 2 + 2 * 64 * VLDS * 2)   // 86016 B

__global__ __launch_bounds__(256, 2)
void pv_kernel(const bf16* __restrict__ Sg, const bf16* __restrict__ Vg,
               const float* __restrict__ x, float* __restrict__ out) {
    extern __shared__ char smem_raw[];
    bf16* sS = (bf16*)smem_raw;            // [2][64][SLDS]
    bf16* sV = sS + 2 * 64 * SLDS;         // [2][64][VLDS]

    int tid  = threadIdx.x;
    int lane = tid & 31;
    int wid  = tid >> 5;
    int b_   = blockIdx.z;
    int rowtile = gridDim.y - 1 - blockIdx.y;
    int row0 = rowtile * 64;
    int col0 = blockIdx.x * 256;
    int warp_m = wid >> 2;                 // 0..1 -> rows [warp_m*32, +32)
    int warp_n = wid & 3;                  // 0..3 -> cols [warp_n*64, +64)
    int ntiles = rowtile + 1;
    int gID = lane >> 2, tig = lane & 3;
    int lsub = lane >> 3, lr = lane & 7;

    const bf16* Sb = Sg + (size_t)b_ * HH * NN * NN;
    const bf16* Vb = Vg + (size_t)b_ * HH * NN * DVV;

    float acc[2][8][4];                    // warp 32x64: 64 regs
    #pragma unroll
    for (int mi = 0; mi < 2; mi++)
        #pragma unroll
        for (int np = 0; np < 8; np++)
            #pragma unroll
            for (int q = 0; q < 4; q++) acc[mi][np][q] = 0.0f;

    auto loadS = [&](bf16* dst, int hh, int mt) {
        const bf16* src = Sb + ((size_t)hh * NN + row0) * NN + mt * 64;
        #pragma unroll
        for (int p = 0; p < 2; p++) {
            int idx = tid + p * 256;
            int r = idx >> 3, c = idx & 7;
            cpa16(&dst[r * SLDS + c * 8], &src[(size_t)r * NN + c * 8]);
        }
    };
    auto loadV = [&](bf16* dst, int hh, int mt) {
        const bf16* src = Vb + ((size_t)hh * NN + mt * 64) * DVV + col0;
        #pragma unroll
        for (int p = 0; p < 8; p++) {
            int idx = tid + p * 256;
            int r = idx >> 5, c = idx & 31;
            cpa16(&dst[r * VLDS + c * 8], &src[(size_t)r * DVV + c * 8]);
        }
    };

    loadS(sS, 0, 0);
    loadV(sV, 0, 0);
    cpa_commit();

    int arow0 = warp_m * 32 + (lsub & 1) * 8 + lr;   // A ldsm row (mi adds 16)
    int acol  = (lsub >> 1) * 8;                     // A ldsm col-in-16
    int vrow  = (lsub & 1) * 8 + lr;                 // V ldsm row-in-16
    int vcol0 = warp_n * 64 + (lsub >> 1) * 8;       // V ldsm col base

    int p = 0;
    for (int h = 0; h < HH; h++) {
        for (int mt = 0; mt < ntiles; mt++) {
            cpa_wait0();
            __syncthreads();

            int nh = h, nmt = mt + 1;
            if (nmt == ntiles) { nh = h + 1; nmt = 0; }
            if (nh < HH) {
                loadS(sS + (p ^ 1) * 64 * SLDS, nh, nmt);
                loadV(sV + (p ^ 1) * 64 * VLDS, nh, nmt);
                cpa_commit();
            }

            bf16* sSc = sS + p * 64 * SLDS;
            bf16* sVc = sV + p * 64 * VLDS;

            #pragma unroll
            for (int k16 = 0; k16 < 4; k16++) {
                // A frags for this k16: 2 ldsm (mi 0,1)
                unsigned a0[4], a1[4];
                ldsm_x4(a0[0], a0[1], a0[2], a0[3],
                        sm32(&sSc[(arow0)      * SLDS + k16 * 16 + acol]));
                ldsm_x4(a1[0], a1[1], a1[2], a1[3],
                        sm32(&sSc[(arow0 + 16) * SLDS + k16 * 16 + acol]));
                // V frags + mma: 4 ldsm_x4_t, 16 mma
                #pragma unroll
                for (int n16 = 0; n16 < 4; n16++) {
                    unsigned v0, v1, v2, v3;
                    ldsm_x4_t(v0, v1, v2, v3,
                              sm32(&sVc[(k16 * 16 + vrow) * VLDS + vcol0 + n16 * 16]));
                    mma_bf16(acc[0][n16 * 2],     a0, v0, v1);
                    mma_bf16(acc[0][n16 * 2 + 1], a0, v2, v3);
                    mma_bf16(acc[1][n16 * 2],     a1, v0, v1);
                    mma_bf16(acc[1][n16 * 2 + 1], a1, v2, v3);
                }
            }
            p ^= 1;
        }
    }

    // epilogue: out = x + acc
    #pragma unroll
    for (int mi = 0; mi < 2; mi++) {
        #pragma unroll
        for (int np = 0; np < 8; np++) {
            int col = col0 + warp_n * 64 + np * 8 + 2 * tig;
            size_t g0 = ((size_t)(b_ * NN + row0 + warp_m * 32 + mi * 16 + gID)) * DVV + col;
            size_t g1 = g0 + (size_t)8 * DVV;
            float2 xa = *(const float2*)(x + g0);
            float2 xb = *(const float2*)(x + g1);
            float2 ra = {xa.x + acc[mi][np][0], xa.y + acc[mi][np][1]};
            float2 rb = {xb.x + acc[mi][np][2], xb.y + acc[mi][np][3]};
            *(float2*)(out + g0) = ra;
            *(float2*)(out + g1) = rb;
        }
    }
}

// ---------------- launch ----------------
extern "C" void kernel_launch(void* const* d_in, const int* in_sizes, int n_in,
                              void* d_out, int out_size) {
    const float* x  = (const float*)d_in[0];
    const float* Wq = (const float*)d_in[1];
    const float* Wk = (const float*)d_in[2];
    const float* Wv = (const float*)d_in[3];
    float* out = (float*)d_out;

    void* p;
    cudaGetSymbolAddress(&p, g_xb); bf16* xb = (bf16*)p;
    cudaGetSymbolAddress(&p, g_wq); bf16* wq = (bf16*)p;
    cudaGetSymbolAddress(&p, g_wk); bf16* wk = (bf16*)p;
    cudaGetSymbolAddress(&p, g_wv); bf16* wv = (bf16*)p;
    cudaGetSymbolAddress(&p, g_Q);  bf16* Q  = (bf16*)p;
    cudaGetSymbolAddress(&p, g_K);  bf16* K  = (bf16*)p;
    cudaGetSymbolAddress(&p, g_V);  bf16* V  = (bf16*)p;
    cudaGetSymbolAddress(&p, g_S);  bf16* S  = (bf16*)p;

    static bool attr_done = false;
    if (!attr_done) {
        cudaFuncSetAttribute(proj_qk_kernel,
            cudaFuncAttributeMaxDynamicSharedMemorySize, PJ_SMEM);
        cudaFuncSetAttribute(proj_v_kernel,
            cudaFuncAttributeMaxDynamicSharedMemorySize, PJ_SMEM);
        cudaFuncSetAttribute(s_kernel,
            cudaFuncAttributeMaxDynamicSharedMemorySize, S_SMEM);
        cudaFuncSetAttribute(pv_kernel,
            cudaFuncAttributeMaxDynamicSharedMemorySize, PV_SMEM);
        attr_done = true;
    }

    cvt_all_kernel<<<2048, 256>>>((const float4*)x,  (__nv_bfloat162*)xb,
                                  (const float4*)Wq, (__nv_bfloat162*)wq,
                                  (const float4*)Wk, (__nv_bfloat162*)wk,
                                  (const float4*)Wv, (__nv_bfloat162*)wv);

    proj_qk_kernel<<<dim3(HH * DKK / 128, BB * NN / 128, 2), 256, PJ_SMEM>>>(xb, wq, wk, Q, K);
    proj_v_kernel <<<dim3(HH * DVV / 128, BB * NN / 128),    256, PJ_SMEM>>>(xb, wv, V);

    s_kernel<<<dim3(136, HH, BB), 256, S_SMEM>>>(Q, K, S);

    pv_kernel<<<dim3(DVV / 256, NN / 64, BB), 256, PV_SMEM>>>(S, V, x, out);
}

// round 12
// speedup vs baseline: 5.8203x; 1.1994x over previous
#include <cuda_runtime.h>
#include <cuda_bf16.h>
#include <cstdint>
#include <cmath>

using bf16 = __nv_bfloat16;

#define BB  2
#define NN  2048
#define DD  1024
#define HH  8
#define DKK 128
#define DVV 1024

// ---------------- static scratch (no allocations allowed) ----------------
__device__ bf16 g_xb[BB * NN * DD];
__device__ bf16 g_wq[HH * DKK * DD];
__device__ bf16 g_wk[HH * DKK * DD];
__device__ bf16 g_wv[HH * DVV * DD];
__device__ bf16 g_Q [BB * HH * NN * DKK];
__device__ bf16 g_K [BB * HH * NN * DKK];
__device__ bf16 g_V [BB * HH * NN * DVV];
__device__ bf16 g_S [(size_t)BB * HH * NN * NN];   // masked-relu scores

// ---------------- asm helpers ----------------
__device__ __forceinline__ void cpa16(void* dst_smem, const void* src_gmem) {
    unsigned d = (unsigned)__cvta_generic_to_shared(dst_smem);
    asm volatile("cp.async.cg.shared.global [%0], [%1], 16;\n" :: "r"(d), "l"(src_gmem));
}
__device__ __forceinline__ void cpa_commit() {
    asm volatile("cp.async.commit_group;\n" ::: "memory");
}
__device__ __forceinline__ void cpa_wait0() {
    asm volatile("cp.async.wait_group 0;\n" ::: "memory");
}
__device__ __forceinline__ unsigned sm32(const void* p) {
    return (unsigned)__cvta_generic_to_shared(p);
}
__device__ __forceinline__ void ldsm_x4(unsigned& r0, unsigned& r1, unsigned& r2,
                                        unsigned& r3, unsigned addr) {
    asm volatile("ldmatrix.sync.aligned.m8n8.x4.shared.b16 {%0,%1,%2,%3}, [%4];\n"
                 : "=r"(r0), "=r"(r1), "=r"(r2), "=r"(r3) : "r"(addr));
}
__device__ __forceinline__ void ldsm_x4_t(unsigned& r0, unsigned& r1, unsigned& r2,
                                          unsigned& r3, unsigned addr) {
    asm volatile("ldmatrix.sync.aligned.m8n8.x4.trans.shared.b16 {%0,%1,%2,%3}, [%4];\n"
                 : "=r"(r0), "=r"(r1), "=r"(r2), "=r"(r3) : "r"(addr));
}
__device__ __forceinline__ void mma_bf16(float c[4], const unsigned a[4],
                                         unsigned b0, unsigned b1) {
    asm volatile("mma.sync.aligned.m16n8k16.row.col.f32.bf16.bf16.f32 "
                 "{%0,%1,%2,%3}, {%4,%5,%6,%7}, {%8,%9}, {%0,%1,%2,%3};\n"
                 : "+f"(c[0]), "+f"(c[1]), "+f"(c[2]), "+f"(c[3])
                 : "r"(a[0]), "r"(a[1]), "r"(a[2]), "r"(a[3]), "r"(b0), "r"(b1));
}
__device__ __forceinline__ unsigned pack_bf2(float lo, float hi) {
    unsigned r;
    asm("cvt.rn.bf16x2.f32 %0, %1, %2;\n" : "=r"(r) : "f"(hi), "f"(lo));
    return r;
}

// ---------------- fused fp32 -> bf16 conversion ----------------
__global__ void cvt_all_kernel(const float4* __restrict__ x,  __nv_bfloat162* __restrict__ xb,
                               const float4* __restrict__ wq, __nv_bfloat162* __restrict__ wqb,
                               const float4* __restrict__ wk, __nv_bfloat162* __restrict__ wkb,
                               const float4* __restrict__ wv, __nv_bfloat162* __restrict__ wvb) {
    const int n0 = BB * NN * DD / 4;
    const int n1 = HH * DKK * DD / 4;
    const int n2 = HH * DVV * DD / 4;
    const int total = n0 + 2 * n1 + n2;
    int i = blockIdx.x * blockDim.x + threadIdx.x;
    int stride = gridDim.x * blockDim.x;
    for (; i < total; i += stride) {
        const float4* src;
        __nv_bfloat162* dst;
        int j = i;
        if (j < n0) { src = x; dst = xb; }
        else if ((j -= n0) < n1) { src = wq; dst = wqb; }
        else if ((j -= n1) < n1) { src = wk; dst = wkb; }
        else { j -= n1; src = wv; dst = wvb; }
        float4 v = src[j];
        dst[2 * j]     = __floats2bfloat162_rn(v.x, v.y);
        dst[2 * j + 1] = __floats2bfloat162_rn(v.z, v.w);
    }
}

// ---------------- projection GEMM (unchanged, passing) ----------------
#define PLDS 72
#define PJ_SMEM (2 * 128 * PLDS * 2 * 2)

__device__ __forceinline__ void proj_body(const bf16* __restrict__ A,
                                          const bf16* __restrict__ W,
                                          bf16* __restrict__ out, int Dh,
                                          int bx, int by) {
    extern __shared__ char smem_raw[];
    bf16* sA = (bf16*)smem_raw;
    bf16* sB = sA + 2 * 128 * PLDS;

    int tid  = threadIdx.x;
    int wid  = tid >> 5;
    int lane = tid & 31;
    int warp_m = wid >> 2;
    int warp_n = wid & 3;
    int rowA0 = by * 128;
    int colB0 = bx * 128;
    int gID = lane >> 2, tig = lane & 3;
    int lsub = lane >> 3, lr = lane & 7;

    float acc[4][4][4];
    #pragma unroll
    for (int mi = 0; mi < 4; mi++)
        #pragma unroll
        for (int nj = 0; nj < 4; nj++)
            #pragma unroll
            for (int q = 0; q < 4; q++) acc[mi][nj][q] = 0.0f;

    auto fill = [&](int buf, int k0) {
        #pragma unroll
        for (int p = 0; p < 8; p++) {
            int idx = tid + p * 256;
            int half = idx >> 10;
            int r  = (idx >> 3) & 127;
            int ch = idx & 7;
            const bf16* src = half ? &W[(size_t)(colB0 + r) * DD + k0 + ch * 8]
                                   : &A[(size_t)(rowA0 + r) * DD + k0 + ch * 8];
            bf16* dst = (half ? sB : sA) + (buf * 128 + r) * PLDS + ch * 8;
            cpa16(dst, src);
        }
        cpa_commit();
    };

    fill(0, 0);
    const int NCH = DD / 64;
    for (int kc = 0; kc < NCH; kc++) {
        int cur = kc & 1;
        cpa_wait0();
        __syncthreads();
        if (kc + 1 < NCH) fill(cur ^ 1, (kc + 1) * 64);

        bf16* pA = sA + cur * 128 * PLDS;
        bf16* pB = sB + cur * 128 * PLDS;
        #pragma unroll
        for (int ks = 0; ks < 2; ks++) {
            unsigned aa[4][2][4];
            #pragma unroll
            for (int mi = 0; mi < 4; mi++)
                #pragma unroll
                for (int kh = 0; kh < 2; kh++) {
                    unsigned addr = sm32(&pA[(warp_m * 64 + mi * 16 + (lsub & 1) * 8 + lr) * PLDS
                                             + ks * 32 + kh * 16 + (lsub >> 1) * 8]);
                    ldsm_x4(aa[mi][kh][0], aa[mi][kh][1], aa[mi][kh][2], aa[mi][kh][3], addr);
                }
            #pragma unroll
            for (int nj = 0; nj < 4; nj++) {
                unsigned b0, b1, b2, b3;
                unsigned addr = sm32(&pB[(warp_n * 32 + nj * 8 + lr) * PLDS + ks * 32 + lsub * 8]);
                ldsm_x4(b0, b1, b2, b3, addr);
                #pragma unroll
                for (int mi = 0; mi < 4; mi++) {
                    mma_bf16(acc[mi][nj], aa[mi][0], b0, b1);
                    mma_bf16(acc[mi][nj], aa[mi][1], b2, b3);
                }
            }
        }
    }

    #pragma unroll
    for (int mi = 0; mi < 4; mi++) {
        int grow0 = rowA0 + warp_m * 64 + mi * 16 + gID;
        #pragma unroll
        for (int half = 0; half < 2; half++) {
            int grow = grow0 + half * 8;
            int b_ = grow >> 11;
            int n_ = grow & 2047;
            #pragma unroll
            for (int nj = 0; nj < 4; nj++) {
                int gcol = colB0 + warp_n * 32 + nj * 8 + 2 * tig;
                int h_ = gcol / Dh;
                int e_ = gcol - h_ * Dh;
                unsigned v = half ? pack_bf2(acc[mi][nj][2], acc[mi][nj][3])
                                  : pack_bf2(acc[mi][nj][0], acc[mi][nj][1]);
                *(unsigned*)(out + (((size_t)b_ * HH + h_) * NN + n_) * Dh + e_) = v;
            }
        }
    }
}

__global__ __launch_bounds__(256)
void proj_qk_kernel(const bf16* __restrict__ A,
                    const bf16* __restrict__ Wq, const bf16* __restrict__ Wk,
                    bf16* __restrict__ Q, bf16* __restrict__ K) {
    if (blockIdx.z == 0) proj_body(A, Wq, Q, DKK, blockIdx.x, blockIdx.y);
    else                 proj_body(A, Wk, K, DKK, blockIdx.x, blockIdx.y);
}

__global__ __launch_bounds__(256)
void proj_v_kernel(const bf16* __restrict__ A, const bf16* __restrict__ Wv,
                   bf16* __restrict__ V) {
    proj_body(A, Wv, V, DVV, blockIdx.x, blockIdx.y);
}

// ---------------- S kernel (unchanged, passing; 55.7us) ----------------
#define KLDS 136
#define S_SMEM (2 * 128 * KLDS * 2)

__global__ __launch_bounds__(256)
void s_kernel(const bf16* __restrict__ Qg, const bf16* __restrict__ Kg,
              bf16* __restrict__ Sg) {
    extern __shared__ char smem_raw[];
    bf16* sQ = (bf16*)smem_raw;
    bf16* sK = sQ + 128 * KLDS;

    int tid  = threadIdx.x;
    int lane = tid & 31;
    int wid  = tid >> 5;
    int h  = blockIdx.y;
    int b_ = blockIdx.z;

    int t = blockIdx.x;
    int rt = (int)((sqrtf(8.0f * (float)t + 1.0f) - 1.0f) * 0.5f);
    while ((rt + 1) * (rt + 2) / 2 <= t) rt++;
    while (rt * (rt + 1) / 2 > t) rt--;
    int ct = t - rt * (rt + 1) / 2;
    int n0 = rt * 128, m0 = ct * 128;

    const bf16* Qp = Qg + ((size_t)(b_ * HH + h) * NN + n0) * DKK;
    const bf16* Kp = Kg + ((size_t)(b_ * HH + h) * NN + m0) * DKK;

    #pragma unroll
    for (int p = 0; p < 8; p++) {
        int idx = tid + p * 256;
        int r = idx >> 4, c = idx & 15;
        cpa16(&sQ[r * KLDS + c * 8], &Qp[(size_t)r * DKK + c * 8]);
        cpa16(&sK[r * KLDS + c * 8], &Kp[(size_t)r * DKK + c * 8]);
    }
    cpa_commit();
    cpa_wait0();
    __syncthreads();

    int rg = wid * 16;
    int gID = lane >> 2, tig = lane & 3;
    int lsub = lane >> 3, lr = lane & 7;

    unsigned qa[8][4];
    int qrow = rg + (lsub & 1) * 8 + lr;
    #pragma unroll
    for (int k = 0; k < 8; k++) {
        unsigned addr = sm32(&sQ[qrow * KLDS + k * 16 + (lsub >> 1) * 8]);
        ldsm_x4(qa[k][0], qa[k][1], qa[k][2], qa[k][3], addr);
    }

    float sc[16][4];
    #pragma unroll
    for (int j = 0; j < 16; j++)
        #pragma unroll
        for (int i = 0; i < 4; i++) sc[j][i] = 0.0f;

    #pragma unroll
    for (int j = 0; j < 16; j++) {
        #pragma unroll
        for (int kp = 0; kp < 4; kp++) {
            unsigned kb0, kb1, kb2, kb3;
            unsigned addr = sm32(&sK[(j * 8 + lr) * KLDS + kp * 32 + lsub * 8]);
            ldsm_x4(kb0, kb1, kb2, kb3, addr);
            mma_bf16(sc[j], qa[2 * kp],     kb0, kb1);
            mma_bf16(sc[j], qa[2 * kp + 1], kb2, kb3);
        }
    }

    const float inv_n = 1.0f / (float)NN;
    bool diag = (rt == ct);
    int rowa = n0 + rg + gID;
    int rowb = rowa + 8;
    bf16* Sp = Sg + (size_t)(b_ * HH + h) * NN * NN;
    #pragma unroll
    for (int j = 0; j < 16; j++) {
        int m = m0 + j * 8 + 2 * tig;
        float v0 = fmaxf(sc[j][0], 0.0f) * inv_n;
        float v1 = fmaxf(sc[j][1], 0.0f) * inv_n;
        float v2 = fmaxf(sc[j][2], 0.0f) * inv_n;
        float v3 = fmaxf(sc[j][3], 0.0f) * inv_n;
        if (diag) {
            if (m     > rowa) v0 = 0.0f;
            if (m + 1 > rowa) v1 = 0.0f;
            if (m     > rowb) v2 = 0.0f;
            if (m + 1 > rowb) v3 = 0.0f;
        }
        *(unsigned*)&Sp[(size_t)rowa * NN + m] = pack_bf2(v0, v1);
        *(unsigned*)&Sp[(size_t)rowb * NN + m] = pack_bf2(v2, v3);
    }
}

// ---------------- PV kernel: out = x + sum_h S @ V (pair-balanced) ----------------
// Grid (colchunk=8 x 128 cols, pair=16, b=2) = 256 CTAs, occ 2 -> one wave.
// CTA y handles rowtiles (31-y) then (y): exactly 33 m-tiles/head for EVERY CTA.
// CTA tile 64x128, 8 warps as 2m x 4n, warp tile 32x32 (acc = 32 regs).
#define SLDS 72
#define VLDS2 136
#define PV_SMEM (2 * 64 * SLDS * 2 + 2 * 64 * VLDS2 * 2)   // 53248 B

__global__ __launch_bounds__(256, 2)
void pv_kernel(const bf16* __restrict__ Sg, const bf16* __restrict__ Vg,
               const float* __restrict__ x, float* __restrict__ out) {
    extern __shared__ char smem_raw[];
    bf16* sS = (bf16*)smem_raw;            // [2][64][SLDS]
    bf16* sV = sS + 2 * 64 * SLDS;         // [2][64][VLDS2]

    int tid  = threadIdx.x;
    int lane = tid & 31;
    int wid  = tid >> 5;
    int b_   = blockIdx.z;
    int py   = blockIdx.y;
    int col0 = blockIdx.x * 128;
    int warp_m = wid >> 2;                 // 0..1 -> rows [warp_m*32, +32)
    int warp_n = wid & 3;                  // 0..3 -> cols [warp_n*32, +32)
    int gID = lane >> 2, tig = lane & 3;
    int lsub = lane >> 3, lr = lane & 7;

    int rt2[2] = {31 - py, py};            // heavy rowtile, then light; 33 tiles total

    const bf16* Sb = Sg + (size_t)b_ * HH * NN * NN;
    const bf16* Vb = Vg + (size_t)b_ * HH * NN * DVV;

    auto loadS = [&](bf16* dst, int row0, int hh, int mt) {
        const bf16* src = Sb + ((size_t)hh * NN + row0) * NN + mt * 64;
        #pragma unroll
        for (int p = 0; p < 2; p++) {
            int idx = tid + p * 256;
            int r = idx >> 3, c = idx & 7;
            cpa16(&dst[r * SLDS + c * 8], &src[(size_t)r * NN + c * 8]);
        }
    };
    auto loadV = [&](bf16* dst, int hh, int mt) {
        const bf16* src = Vb + ((size_t)hh * NN + mt * 64) * DVV + col0;
        #pragma unroll
        for (int p = 0; p < 4; p++) {
            int idx = tid + p * 256;
            int r = idx >> 4, c = idx & 15;
            cpa16(&dst[r * VLDS2 + c * 8], &src[(size_t)r * DVV + c * 8]);
        }
    };

    int arow0 = warp_m * 32 + (lsub & 1) * 8 + lr;   // A ldsm row (mi adds 16)
    int acol  = (lsub >> 1) * 8;
    int vrow  = (lsub & 1) * 8 + lr;
    int vcol0 = warp_n * 32 + (lsub >> 1) * 8;

    loadS(sS, rt2[0] * 64, 0, 0);
    loadV(sV, 0, 0);
    cpa_commit();

    int p = 0;
    for (int pi = 0; pi < 2; pi++) {
        int rowtile = rt2[pi];
        int row0 = rowtile * 64;
        int ntiles = rowtile + 1;

        float acc[2][4][4];
        #pragma unroll
        for (int mi = 0; mi < 2; mi++)
            #pragma unroll
            for (int nj = 0; nj < 4; nj++)
                #pragma unroll
                for (int q = 0; q < 4; q++) acc[mi][nj][q] = 0.0f;

        for (int h = 0; h < HH; h++) {
            for (int mt = 0; mt < ntiles; mt++) {
                cpa_wait0();
                __syncthreads();

                // next iteration coords (crossing the pair boundary seamlessly)
                int npi = pi, nh = h, nmt = mt + 1;
                if (nmt == ntiles) { nmt = 0; nh++; if (nh == HH) { nh = 0; npi++; } }
                if (npi < 2) {
                    loadS(sS + (p ^ 1) * 64 * SLDS, rt2[npi] * 64, nh, nmt);
                    loadV(sV + (p ^ 1) * 64 * VLDS2, nh, nmt);
                    cpa_commit();
                }

                bf16* sSc = sS + p * 64 * SLDS;
                bf16* sVc = sV + p * 64 * VLDS2;

                #pragma unroll
                for (int k16 = 0; k16 < 4; k16++) {
                    unsigned a0[4], a1[4];
                    ldsm_x4(a0[0], a0[1], a0[2], a0[3],
                            sm32(&sSc[(arow0)      * SLDS + k16 * 16 + acol]));
                    ldsm_x4(a1[0], a1[1], a1[2], a1[3],
                            sm32(&sSc[(arow0 + 16) * SLDS + k16 * 16 + acol]));
                    #pragma unroll
                    for (int n16 = 0; n16 < 2; n16++) {
                        unsigned v0, v1, v2, v3;
                        ldsm_x4_t(v0, v1, v2, v3,
                                  sm32(&sVc[(k16 * 16 + vrow) * VLDS2 + vcol0 + n16 * 16]));
                        mma_bf16(acc[0][n16 * 2],     a0, v0, v1);
                        mma_bf16(acc[0][n16 * 2 + 1], a0, v2, v3);
                        mma_bf16(acc[1][n16 * 2],     a1, v0, v1);
                        mma_bf16(acc[1][n16 * 2 + 1], a1, v2, v3);
                    }
                }
                p ^= 1;
            }
        }

        // epilogue for this rowtile: out = x + acc
        #pragma unroll
        for (int mi = 0; mi < 2; mi++) {
            #pragma unroll
            for (int nj = 0; nj < 4; nj++) {
                int col = col0 + warp_n * 32 + nj * 8 + 2 * tig;
                size_t g0 = ((size_t)(b_ * NN + row0 + warp_m * 32 + mi * 16 + gID)) * DVV + col;
                size_t g1 = g0 + (size_t)8 * DVV;
                float2 xa = *(const float2*)(x + g0);
                float2 xb = *(const float2*)(x + g1);
                float2 ra = {xa.x + acc[mi][nj][0], xa.y + acc[mi][nj][1]};
                float2 rb = {xb.x + acc[mi][nj][2], xb.y + acc[mi][nj][3]};
                *(float2*)(out + g0) = ra;
                *(float2*)(out + g1) = rb;
            }
        }
    }
}

// ---------------- launch ----------------
extern "C" void kernel_launch(void* const* d_in, const int* in_sizes, int n_in,
                              void* d_out, int out_size) {
    const float* x  = (const float*)d_in[0];
    const float* Wq = (const float*)d_in[1];
    const float* Wk = (const float*)d_in[2];
    const float* Wv = (const float*)d_in[3];
    float* out = (float*)d_out;

    void* p;
    cudaGetSymbolAddress(&p, g_xb); bf16* xb = (bf16*)p;
    cudaGetSymbolAddress(&p, g_wq); bf16* wq = (bf16*)p;
    cudaGetSymbolAddress(&p, g_wk); bf16* wk = (bf16*)p;
    cudaGetSymbolAddress(&p, g_wv); bf16* wv = (bf16*)p;
    cudaGetSymbolAddress(&p, g_Q);  bf16* Q  = (bf16*)p;
    cudaGetSymbolAddress(&p, g_K);  bf16* K  = (bf16*)p;
    cudaGetSymbolAddress(&p, g_V);  bf16* V  = (bf16*)p;
    cudaGetSymbolAddress(&p, g_S);  bf16* S  = (bf16*)p;

    static bool attr_done = false;
    if (!attr_done) {
        cudaFuncSetAttribute(proj_qk_kernel,
            cudaFuncAttributeMaxDynamicSharedMemorySize, PJ_SMEM);
        cudaFuncSetAttribute(proj_v_kernel,
            cudaFuncAttributeMaxDynamicSharedMemorySize, PJ_SMEM);
        cudaFuncSetAttribute(s_kernel,
            cudaFuncAttributeMaxDynamicSharedMemorySize, S_SMEM);
        cudaFuncSetAttribute(pv_kernel,
            cudaFuncAttributeMaxDynamicSharedMemorySize, PV_SMEM);
        attr_done = true;
    }

    cvt_all_kernel<<<2048, 256>>>((const float4*)x,  (__nv_bfloat162*)xb,
                                  (const float4*)Wq, (__nv_bfloat162*)wq,
                                  (const float4*)Wk, (__nv_bfloat162*)wk,
                                  (const float4*)Wv, (__nv_bfloat162*)wv);

    proj_qk_kernel<<<dim3(HH * DKK / 128, BB * NN / 128, 2), 256, PJ_SMEM>>>(xb, wq, wk, Q, K);
    proj_v_kernel <<<dim3(HH * DVV / 128, BB * NN / 128),    256, PJ_SMEM>>>(xb, wv, V);

    s_kernel<<<dim3(136, HH, BB), 256, S_SMEM>>>(Q, K, S);

    pv_kernel<<<dim3(DVV / 128, 16, BB), 256, PV_SMEM>>>(S, V, x, out);
}